// round 5
// baseline (speedup 1.0000x reference)
#include <cuda_runtime.h>
#include <math.h>
#include <stdint.h>

#define NBLK 3
#define BD 8
#define HWQ 4096   // 64*64
#define NCH 64     // NC (channels per DAT block)
#define NS  256    // Hk*Wk = 16*16
#define HCD 16     // head channels
#define TABN 16129 // 127*127
#define TABP 16384 // padded dual-table stride

// ---- static device scratch (no runtime allocation allowed) ----
__device__ float  g_Q[NBLK*BD*NCH*HWQ];   // q projections      [blk][b][c][hw]
__device__ float  g_O[NBLK*BD*NCH*HWQ];   // attention outputs  [blk][b][c][hw]
__device__ float  g_K[NBLK*BD*NCH*NS];    // keys   [blk][b][c][n]
__device__ float  g_V[NBLK*BD*NCH*NS];    // values [blk][b][c][n]
__device__ float4 g_BP[NBLK*BD*NS];       // bias params per n: (y0*127+x0, wy, wx, 0)
__device__ float2 g_POS[NBLK*BD*NS];      // normalized sample pos (py,px)
__device__ float  g_DW[NBLK*BD*NCH*NS];   // dwconv output [blk][b][c][n]
__device__ float2 g_TAB2[NBLK*4*TABP];    // dual RPE tables: (t[i], t[i+1]), zero-padded

// ---- tf32 mma helpers ----
__device__ __forceinline__ uint32_t f2tf(float f) {
    uint32_t r; asm("cvt.rna.tf32.f32 %0, %1;" : "=r"(r) : "f"(f)); return r;
}
__device__ __forceinline__ void mma_tf32(float* c, const uint32_t* a, const uint32_t* b) {
    asm volatile(
        "mma.sync.aligned.m16n8k8.row.col.f32.tf32.tf32.f32 "
        "{%0,%1,%2,%3}, {%4,%5,%6,%7}, {%8,%9}, {%0,%1,%2,%3};"
        : "+f"(c[0]), "+f"(c[1]), "+f"(c[2]), "+f"(c[3])
        : "r"(a[0]), "r"(a[1]), "r"(a[2]), "r"(a[3]), "r"(b[0]), "r"(b[1]));
}

// ============================================================================
// Kernel T: build dual tables. grid = 12 tables * 8 chunks = 96
// ============================================================================
__global__ __launch_bounds__(256) void k_tab2(const float* __restrict__ rpe)
{
    int t = blockIdx.x >> 3, q = blockIdx.x & 7;
    const float* src = rpe + (size_t)t * TABN;
    float2* dst = g_TAB2 + (size_t)t * TABP;
    #pragma unroll
    for (int k = 0; k < 8; ++k) {
        int i = q*2048 + k*256 + threadIdx.x;
        float a = (i < TABN)     ? src[i]   : 0.f;
        float b = (i+1 < TABN)   ? src[i+1] : 0.f;
        dst[i] = make_float2(a, b);
    }
}

// ============================================================================
// Kernel A: q = pq_w @ x[:, :64] + pq_b      (3 blocks; blk0<-x1, blk1/2<-x2)
// grid = 384, 256 threads, 1 hw per thread
// ============================================================================
__global__ __launch_bounds__(256) void k_qproj(
    const float* __restrict__ x1, const float* __restrict__ x2,
    const float* __restrict__ pqw, const float* __restrict__ pqb)
{
    __shared__ float wsT[64*64];
    __shared__ float bs[64];
    int bx = blockIdx.x;
    int tile = bx & 15, b = (bx >> 4) & 7, blk = bx >> 7;
    const float* xin = (blk == 0 ? x1 : x2) + (size_t)b * 128 * HWQ;

    for (int i = threadIdx.x; i < 4096; i += 256) {
        int c = i >> 6, o = i & 63;
        wsT[c*64 + o] = pqw[blk*4096 + o*64 + c];
    }
    if (threadIdx.x < 64) bs[threadIdx.x] = pqb[blk*64 + threadIdx.x];
    __syncthreads();

    int hw = tile*256 + threadIdx.x;
    float* qout = g_Q + (size_t)(blk*BD + b) * NCH * HWQ;

    float acc[64];
    #pragma unroll
    for (int o = 0; o < 64; ++o) acc[o] = bs[o];
    #pragma unroll 2
    for (int c = 0; c < 64; ++c) {
        float xv = __ldg(&xin[c*HWQ + hw]);
        const float4* wr = reinterpret_cast<const float4*>(&wsT[c*64]);
        #pragma unroll
        for (int o4 = 0; o4 < 16; ++o4) {
            float4 w = wr[o4];
            acc[o4*4+0] = fmaf(w.x, xv, acc[o4*4+0]);
            acc[o4*4+1] = fmaf(w.y, xv, acc[o4*4+1]);
            acc[o4*4+2] = fmaf(w.z, xv, acc[o4*4+2]);
            acc[o4*4+3] = fmaf(w.w, xv, acc[o4*4+3]);
        }
    }
    #pragma unroll
    for (int o = 0; o < 64; ++o) qout[o*HWQ + hw] = acc[o];
}

// ============================================================================
// Kernel B1: depthwise conv 4x4 s4 on q plane, smem-staged (coalesced).
// grid = 384 (3 blk * 8 b * 16 c-chunks of 4ch), 256 threads (one per n)
// ============================================================================
__global__ __launch_bounds__(256) void k_dw(
    const float* __restrict__ dww, const float* __restrict__ dwb)
{
    __shared__ float sq[4*HWQ];
    int bx = blockIdx.x;
    int cchunk = bx & 15, b = (bx >> 4) & 7, blk = bx >> 7;
    int c0 = cchunk * 4;
    int tid = threadIdx.x;
    const float* qsrc = g_Q + ((size_t)(blk*BD + b)*NCH + c0) * HWQ;

    for (int i = tid; i < 4096; i += 256)
        reinterpret_cast<float4*>(sq)[i] = reinterpret_cast<const float4*>(qsrc)[i];
    __syncthreads();

    int oy = tid >> 4, ox = tid & 15;
    float* dwp = g_DW + ((size_t)(blk*BD + b)*NCH + c0) * NS;
    #pragma unroll
    for (int cc = 0; cc < 4; ++cc) {
        int c = c0 + cc;
        float a = __ldg(&dwb[blk*64 + c]);
        const float* w = dww + blk*NCH*16 + c*16;
        const float* sp = sq + cc*HWQ + oy*256 + ox*4;
        #pragma unroll
        for (int ky = 0; ky < 4; ++ky)
            #pragma unroll
            for (int kx = 0; kx < 4; ++kx)
                a = fmaf(sp[ky*64 + kx], __ldg(&w[ky*4 + kx]), a);
        dwp[cc*NS + tid] = a;
    }
}

// ============================================================================
// Kernel B2: LN -> GELU -> 1x1 -> offsets -> pos + bias params.
// Two-pass (no local array -> no spills). grid = 24, 256 threads (one per n)
// ============================================================================
__global__ __launch_bounds__(256) void k_off2(
    const float* __restrict__ lng, const float* __restrict__ lnb,
    const float* __restrict__ pww)
{
    int bx = blockIdx.x;
    int b = bx & 7, blk = bx >> 3;
    int n = threadIdx.x;
    int oy = n >> 4, ox = n & 15;
    const float* dwp = g_DW + (size_t)(blk*BD + b)*NCH*NS;

    float s1 = 0.f, s2 = 0.f;
    #pragma unroll 8
    for (int c = 0; c < 64; ++c) {
        float a = dwp[c*NS + n];
        s1 += a; s2 += a*a;
    }
    float mu  = s1 * (1.f/64.f);
    float var = s2 * (1.f/64.f) - mu*mu;
    float rs  = rsqrtf(var + 1e-5f);

    float offy = 0.f, offx = 0.f;
    #pragma unroll 4
    for (int c = 0; c < 64; ++c) {
        float a = dwp[c*NS + n];
        float t = (a - mu) * rs * __ldg(&lng[blk*64 + c]) + __ldg(&lnb[blk*64 + c]);
        float gl = 0.5f * t * (1.f + erff(t * 0.70710678118654752f));
        offy = fmaf(__ldg(&pww[blk*128 + c]),      gl, offy);
        offx = fmaf(__ldg(&pww[blk*128 + 64 + c]), gl, offx);
    }
    float refy = (2.f*((float)oy + 0.5f)) * (1.f/15.f) - 1.f;
    float refx = (2.f*((float)ox + 0.5f)) * (1.f/15.f) - 1.f;
    float py = fminf(fmaxf(offy + refy, -1.f), 1.f);
    float px = fminf(fmaxf(offx + refx, -1.f), 1.f);

    float ay = 31.5f*(1.f - py), ax = 31.5f*(1.f - px);
    float by0 = floorf(ay), bx0 = floorf(ax);
    g_BP[(blk*BD + b)*NS + n]  = make_float4(by0*127.f + bx0, ay - by0, ax - bx0, 0.f);
    g_POS[(blk*BD + b)*NS + n] = make_float2(py, px);
}

// ============================================================================
// Kernel B3: deformable gather + k/v projections.
// grid = 96 (3 blk * 8 b * 4 n-chunks of 64), 256 threads = (nl 64, cg 4)
// ============================================================================
__global__ __launch_bounds__(256) void k_gkv(
    const float* __restrict__ x0, const float* __restrict__ x1,
    const float* __restrict__ pkw, const float* __restrict__ pkb,
    const float* __restrict__ pvw, const float* __restrict__ pvb)
{
    extern __shared__ float sm[];
    float* buf = sm;              // [64][65]
    float* skw = sm + 64*65;      // 4096
    float* svw = skw + 4096;      // 4096

    int bx = blockIdx.x;
    int nc = bx & 3, b = (bx >> 2) & 7, blk = bx >> 5;
    const float* kvsrc = (blk == 2 ? x1 : x0) + (size_t)b * 128 * HWQ;
    int tid = threadIdx.x;
    int nl = tid & 63, cg = tid >> 6;
    int n = nc*64 + nl;

    for (int i = tid; i < 4096; i += 256) {
        skw[i] = pkw[blk*4096 + i];
        svw[i] = pvw[blk*4096 + i];
    }

    float2 pos = g_POS[(blk*BD + b)*NS + n];
    float sy = (pos.x + 1.f)*31.5f, sx = (pos.y + 1.f)*31.5f;
    float fy = floorf(sy), fx = floorf(sx);
    int iy0 = (int)fy, ix0 = (int)fx;
    float wby = sy - fy, wbx = sx - fx;
    int iy1 = min(iy0 + 1, 63), ix1 = min(ix0 + 1, 63);
    float w00 = (1.f-wby)*(1.f-wbx), w01 = (1.f-wby)*wbx;
    float w10 = wby*(1.f-wbx),       w11 = wby*wbx;
    #pragma unroll 4
    for (int cc = 0; cc < 16; ++cc) {
        int c = cg*16 + cc;
        const float* ip = kvsrc + c*HWQ;
        float val = w00*__ldg(&ip[iy0*64 + ix0]) + w01*__ldg(&ip[iy0*64 + ix1])
                  + w10*__ldg(&ip[iy1*64 + ix0]) + w11*__ldg(&ip[iy1*64 + ix1]);
        buf[nl*65 + c] = val;
    }
    __syncthreads();

    float* kout = g_K + (size_t)(blk*BD + b)*NCH*NS;
    float* vout = g_V + (size_t)(blk*BD + b)*NCH*NS;
    #pragma unroll 2
    for (int oo = 0; oo < 16; ++oo) {
        int o = cg*16 + oo;
        float ak = __ldg(&pkb[blk*64 + o]);
        float av = __ldg(&pvb[blk*64 + o]);
        #pragma unroll 8
        for (int c = 0; c < 64; ++c) {
            float xv = buf[nl*65 + c];
            ak = fmaf(skw[o*64 + c], xv, ak);
            av = fmaf(svw[o*64 + c], xv, av);
        }
        kout[o*NS + n] = ak;
        vout[o*NS + n] = av;
    }
}

// ============================================================================
// Kernel D: tensor-core attention (tf32 mma.sync m16n8k8).
// CTA = (bb, head, 128-query tile = 2 image rows). 256 threads = 8 warps.
// Pipeline per 64-key chunk: QK mma -> Ps[n][m] smem -> coalesced bias+exp
// (dual-table taps, pair-row sharing) -> PV mma (P read back as A-frags).
// smem layout (floats):
//   Ks[16][264]   @0      (16.9KB)  conflict-free B-frag loads
//   Vs[256][24]   @4224   (24.6KB)  conflict-free B-frag loads
//   Ps[64][132]   @10368  (33.8KB)  conflict-free STS(c-frag) + coalesced LDS
//   pp4[256]      @18816  (4KB)
//   sp[512]       @19840, sinv[128] @20352  -> total 81920 B
// ============================================================================
#define KS_OFF 0
#define VS_OFF 4224
#define PS_OFF 10368
#define PP_OFF 18816
#define SP_OFF 19840
#define SI_OFF 20352
#define ATTN_SMEM (20480*4)

__global__ __launch_bounds__(256, 2) void k_attn()
{
    extern __shared__ float sm[];
    float*  Ks   = sm + KS_OFF;
    float*  Vs   = sm + VS_OFF;
    float*  Ps   = sm + PS_OFF;
    float4* pp4  = (float4*)(sm + PP_OFF);
    float*  sp   = sm + SP_OFF;
    float*  sinv = sm + SI_OFF;

    int bx = blockIdx.x;
    int mt = bx & 31, head = (bx >> 5) & 3, bb = bx >> 7;   // bb = blk*8+b
    int tid = threadIdx.x;
    int warp = tid >> 5, lane = tid & 31;
    int r = lane >> 2, cg = lane & 3;
    int ml0 = warp*16 + r;          // local m row (0..127) for fragment rows
    int y0 = mt*2;                  // first image row of this tile

    const float2* tab = g_TAB2 + (size_t)((bb >> 3)*4 + head) * TABP;

    // ---- stage K, V (tf32-converted), bias params ----
    const float* kg = g_K + (size_t)(bb*NCH + head*HCD) * NS;
    const float* vg = g_V + (size_t)(bb*NCH + head*HCD) * NS;
    for (int i = tid; i < 4096; i += 256) {
        int k = i >> 8, n = i & 255;
        Ks[k*264 + n] = __uint_as_float(f2tf(kg[k*NS + n]));
    }
    for (int i = tid; i < 4096; i += 256) {
        int c = i >> 8, n = i & 255;
        Vs[n*24 + c] = __uint_as_float(f2tf(vg[c*NS + n]));
    }
    {
        float4 bp = g_BP[bb*NS + tid];
        float wy = bp.y, wx = bp.z;
        pp4[tid] = make_float4((1.f-wy)*(1.f-wx), (1.f-wy)*wx, wy*(1.f-wx), bp.x);
    }

    // ---- Q fragments (0.25 scale folded in) ----
    const float* qg = g_Q + (size_t)(bb*NCH + head*HCD) * HWQ + mt*128;
    uint32_t qa[2][4];
    #pragma unroll
    for (int s = 0; s < 2; ++s) {
        qa[s][0] = f2tf(0.25f * qg[(s*8+cg  )*HWQ + ml0    ]);
        qa[s][1] = f2tf(0.25f * qg[(s*8+cg  )*HWQ + ml0 + 8]);
        qa[s][2] = f2tf(0.25f * qg[(s*8+cg+4)*HWQ + ml0    ]);
        qa[s][3] = f2tf(0.25f * qg[(s*8+cg+4)*HWQ + ml0 + 8]);
    }
    __syncthreads();

    float oacc[2][4];
    #pragma unroll
    for (int ct = 0; ct < 2; ++ct)
        #pragma unroll
        for (int j = 0; j < 4; ++j) oacc[ct][j] = 0.f;
    float ss1 = 0.f, ss2 = 0.f;
    int xs = tid & 63, ngs = tid >> 6;
    int rb = y0*127 + xs;

    for (int ch = 0; ch < 4; ++ch) {
        // ---- QK^T: S chunk (128m x 64n) ----
        #pragma unroll
        for (int nt = 0; nt < 8; ++nt) {
            float c4[4] = {0.f, 0.f, 0.f, 0.f};
            #pragma unroll
            for (int s = 0; s < 2; ++s) {
                uint32_t b2[2];
                b2[0] = __float_as_uint(Ks[(s*8+cg  )*264 + ch*64 + nt*8 + r]);
                b2[1] = __float_as_uint(Ks[(s*8+cg+4)*264 + ch*64 + nt*8 + r]);
                mma_tf32(c4, qa[s], b2);
            }
            int nb = nt*8 + 2*cg;
            Ps[ nb   *132 + ml0    ] = c4[0];
            Ps[(nb+1)*132 + ml0    ] = c4[1];
            Ps[ nb   *132 + ml0 + 8] = c4[2];
            Ps[(nb+1)*132 + ml0 + 8] = c4[3];
        }
        __syncthreads();

        // ---- bias + exp (coalesced: consecutive lanes = consecutive m) ----
        #pragma unroll 4
        for (int j = 0; j < 16; ++j) {
            int nl = ngs*16 + j;
            float4 pp = pp4[ch*64 + nl];
            int o = (int)pp.w + rb;
            float w11 = 1.f - pp.x - pp.y - pp.z;
            float2 t0 = __ldg(&tab[o]);
            float2 t1 = __ldg(&tab[o + 127]);
            float2 t2 = __ldg(&tab[o + 254]);
            float b1 = pp.x * t0.x;
            b1 = fmaf(pp.y, t0.y, b1); b1 = fmaf(pp.z, t1.x, b1); b1 = fmaf(w11, t1.y, b1);
            float b2 = pp.x * t1.x;
            b2 = fmaf(pp.y, t1.y, b2); b2 = fmaf(pp.z, t2.x, b2); b2 = fmaf(w11, t2.y, b2);
            float p1 = __expf(Ps[nl*132 + xs] + b1);
            float p2 = __expf(Ps[nl*132 + 64 + xs] + b2);
            Ps[nl*132 + xs]      = p1;
            Ps[nl*132 + 64 + xs] = p2;
            ss1 += p1; ss2 += p2;
        }
        __syncthreads();

        // ---- PV: acc += P_chunk @ V_chunk ----
        #pragma unroll
        for (int ks = 0; ks < 8; ++ks) {
            uint32_t a4[4];
            a4[0] = f2tf(Ps[(ks*8+cg  )*132 + ml0    ]);
            a4[1] = f2tf(Ps[(ks*8+cg  )*132 + ml0 + 8]);
            a4[2] = f2tf(Ps[(ks*8+cg+4)*132 + ml0    ]);
            a4[3] = f2tf(Ps[(ks*8+cg+4)*132 + ml0 + 8]);
            int nglob = ch*64 + ks*8;
            #pragma unroll
            for (int ct = 0; ct < 2; ++ct) {
                uint32_t b2[2];
                b2[0] = __float_as_uint(Vs[(nglob+cg  )*24 + ct*8 + r]);
                b2[1] = __float_as_uint(Vs[(nglob+cg+4)*24 + ct*8 + r]);
                mma_tf32(oacc[ct], a4, b2);
            }
        }
        __syncthreads();
    }

    // ---- row sums -> inverse ----
    sp[ngs*128 + xs]      = ss1;
    sp[ngs*128 + 64 + xs] = ss2;
    __syncthreads();
    if (tid < 128)
        sinv[tid] = 1.f / (sp[tid] + sp[128+tid] + sp[256+tid] + sp[384+tid]);
    __syncthreads();

    // ---- write normalized output ----
    float* og = g_O + (size_t)(bb*NCH + head*HCD) * HWQ + mt*128;
    float i0 = sinv[ml0], i8 = sinv[ml0 + 8];
    #pragma unroll
    for (int ct = 0; ct < 2; ++ct) {
        int c = ct*8 + 2*cg;
        og[ c   *HWQ + ml0    ] = oacc[ct][0] * i0;
        og[(c+1)*HWQ + ml0    ] = oacc[ct][1] * i0;
        og[ c   *HWQ + ml0 + 8] = oacc[ct][2] * i8;
        og[(c+1)*HWQ + ml0 + 8] = oacc[ct][3] * i8;
    }
}

// ============================================================================
// Kernel E: final assembly. grid = 384, 256 threads, 1 hw per thread.
// ============================================================================
__global__ __launch_bounds__(256) void k_out(
    const float* __restrict__ x0, const float* __restrict__ x1,
    const float* __restrict__ x2,
    const float* __restrict__ poww, const float* __restrict__ pob,
    float* __restrict__ out)
{
    __shared__ float wsT[2][64*64];
    __shared__ float bsum[64];
    int bx = blockIdx.x;
    int tile = bx & 15, b = (bx >> 4) & 7, lvl = bx >> 7;
    const float* xl = (lvl == 0 ? x0 : (lvl == 1 ? x1 : x2)) + (size_t)b * 128 * HWQ;
    float* outp = out + (size_t)(lvl*BD + b) * 128 * HWQ;
    int hw = tile*256 + threadIdx.x;

    #pragma unroll 4
    for (int c = 0; c < 64; ++c)
        outp[c*HWQ + hw] = __ldg(&xl[c*HWQ + hw]);

    if (lvl == 0) {
        #pragma unroll 4
        for (int c = 64; c < 128; ++c)
            outp[c*HWQ + hw] = __ldg(&xl[c*HWQ + hw]);
        return;
    }

    int blk0 = (lvl == 1) ? 0 : 1;
    int nb   = (lvl == 1) ? 1 : 2;

    for (int i = threadIdx.x; i < 4096; i += 256) {
        int c = i >> 6, o = i & 63;
        wsT[0][c*64 + o] = poww[blk0*4096 + o*64 + c];
        if (nb == 2) wsT[1][c*64 + o] = poww[(blk0+1)*4096 + o*64 + c];
    }
    if (threadIdx.x < 64) {
        float s = pob[blk0*64 + threadIdx.x];
        if (nb == 2) s += pob[(blk0+1)*64 + threadIdx.x];
        bsum[threadIdx.x] = s;
    }
    __syncthreads();

    const float* o0 = g_O + (size_t)(blk0*BD + b) * NCH * HWQ;
    const float* o1 = g_O + (size_t)((blk0+1)*BD + b) * NCH * HWQ;

    float acc[64];
    #pragma unroll
    for (int o = 0; o < 64; ++o)
        acc[o] = __ldg(&xl[(64 + o)*HWQ + hw]) + bsum[o];

    #pragma unroll 2
    for (int c = 0; c < 64; ++c) {
        float a0 = o0[c*HWQ + hw];
        const float4* wr = reinterpret_cast<const float4*>(&wsT[0][c*64]);
        #pragma unroll
        for (int o4 = 0; o4 < 16; ++o4) {
            float4 w = wr[o4];
            acc[o4*4+0] = fmaf(w.x, a0, acc[o4*4+0]);
            acc[o4*4+1] = fmaf(w.y, a0, acc[o4*4+1]);
            acc[o4*4+2] = fmaf(w.z, a0, acc[o4*4+2]);
            acc[o4*4+3] = fmaf(w.w, a0, acc[o4*4+3]);
        }
    }
    if (nb == 2) {
        #pragma unroll 2
        for (int c = 0; c < 64; ++c) {
            float a1 = o1[c*HWQ + hw];
            const float4* wr = reinterpret_cast<const float4*>(&wsT[1][c*64]);
            #pragma unroll
            for (int o4 = 0; o4 < 16; ++o4) {
                float4 w = wr[o4];
                acc[o4*4+0] = fmaf(w.x, a1, acc[o4*4+0]);
                acc[o4*4+1] = fmaf(w.y, a1, acc[o4*4+1]);
                acc[o4*4+2] = fmaf(w.z, a1, acc[o4*4+2]);
                acc[o4*4+3] = fmaf(w.w, a1, acc[o4*4+3]);
            }
        }
    }
    #pragma unroll
    for (int o = 0; o < 64; ++o)
        outp[(64 + o)*HWQ + hw] = acc[o];
}

// ============================================================================
extern "C" void kernel_launch(void* const* d_in, const int* in_sizes, int n_in,
                              void* d_out, int out_size)
{
    const float* x0  = (const float*)d_in[0];
    const float* x1  = (const float*)d_in[1];
    const float* x2  = (const float*)d_in[2];
    const float* pqw = (const float*)d_in[3];
    const float* pqb = (const float*)d_in[4];
    const float* dww = (const float*)d_in[5];
    const float* dwb = (const float*)d_in[6];
    const float* lng = (const float*)d_in[7];
    const float* lnb = (const float*)d_in[8];
    const float* pww = (const float*)d_in[9];
    const float* pkw = (const float*)d_in[10];
    const float* pkb = (const float*)d_in[11];
    const float* pvw = (const float*)d_in[12];
    const float* pvb = (const float*)d_in[13];
    const float* pow_ = (const float*)d_in[14];
    const float* pob = (const float*)d_in[15];
    const float* rpe = (const float*)d_in[16];

    const int gkv_smem = (64*65 + 4096 + 4096) * 4;        // 49408 B
    cudaFuncSetAttribute(k_gkv,  cudaFuncAttributeMaxDynamicSharedMemorySize, gkv_smem);
    cudaFuncSetAttribute(k_attn, cudaFuncAttributeMaxDynamicSharedMemorySize, ATTN_SMEM);

    k_tab2<<<96, 256>>>(rpe);
    k_qproj<<<384, 256>>>(x1, x2, pqw, pqb);
    k_dw<<<384, 256>>>(dww, dwb);
    k_off2<<<24, 256>>>(lng, lnb, pww);
    k_gkv<<<96, 256, gkv_smem>>>(x0, x1, pkw, pkb, pvw, pvb);
    k_attn<<<3072, 256, ATTN_SMEM>>>();
    k_out<<<384, 256>>>(x0, x1, x2, pow_, pob, (float*)d_out);
}

// round 6
// speedup vs baseline: 1.1356x; 1.1356x over previous
#include <cuda_runtime.h>
#include <math.h>
#include <stdint.h>

#define NBLK 3
#define BD 8
#define HWQ 4096   // 64*64
#define NCH 64     // NC (channels per DAT block)
#define NS  256    // Hk*Wk = 16*16
#define HCD 16     // head channels
#define TABN 16129 // 127*127
#define TABP 16384 // padded dual-table stride

// ---- static device scratch (no runtime allocation allowed) ----
__device__ float  g_Q[NBLK*BD*NCH*HWQ];   // q projections      [blk][b][c][hw]
__device__ float  g_O[NBLK*BD*NCH*HWQ];   // attention outputs  [blk][b][c][hw]
__device__ float  g_K[NBLK*BD*NCH*NS];    // keys   [blk][b][c][n]
__device__ float  g_V[NBLK*BD*NCH*NS];    // values [blk][b][c][n]
__device__ float4 g_BP[NBLK*BD*NS];       // bias params per n: (y0*127+x0, wy, wx, 0)
__device__ float2 g_POS[NBLK*BD*NS];      // normalized sample pos (py,px)
__device__ float  g_DW[NBLK*BD*NS*NCH];   // dwconv output [bb][n][c]  (c contiguous!)
__device__ float2 g_TAB2[NBLK*4*TABP];    // dual RPE tables: (t[i], t[i+1]), zero-padded

// ============================================================================
// Kernel T: build dual tables. grid = 12 tables * 8 chunks = 96
// ============================================================================
__global__ __launch_bounds__(256) void k_tab2(const float* __restrict__ rpe)
{
    int t = blockIdx.x >> 3, q = blockIdx.x & 7;
    const float* src = rpe + (size_t)t * TABN;
    float2* dst = g_TAB2 + (size_t)t * TABP;
    #pragma unroll
    for (int k = 0; k < 8; ++k) {
        int i = q*2048 + k*256 + threadIdx.x;
        float a = (i < TABN)     ? src[i]   : 0.f;
        float b = (i+1 < TABN)   ? src[i+1] : 0.f;
        dst[i] = make_float2(a, b);
    }
}

// ============================================================================
// Kernel A: q-projection FUSED with depthwise conv 4x4 s4.
// grid = 384 (3 blk * 8 b * 16 tiles of 256 hw = 4 image rows), 256 threads.
// Tile of 4 image rows == exactly one dwconv output row (oy = tile).
// ============================================================================
__global__ __launch_bounds__(256) void k_qproj_dw(
    const float* __restrict__ x1, const float* __restrict__ x2,
    const float* __restrict__ pqw, const float* __restrict__ pqb,
    const float* __restrict__ dww, const float* __restrict__ dwb)
{
    __shared__ float wsT[64*64];   // 16 KB  wsT[c][o] = w[o][c]
    __shared__ float bs[64];
    __shared__ float sq[16*256];   // 16 KB  one 16-channel quarter of the q tile
    __shared__ float swdw[64*16];  // 4 KB   dw weights
    __shared__ float sdwb[64];

    int bx = blockIdx.x;
    int tile = bx & 15, b = (bx >> 4) & 7, blk = bx >> 7;
    int bb = blk*BD + b;
    const float* xin = (blk == 0 ? x1 : x2) + (size_t)b * 128 * HWQ;
    int tid = threadIdx.x;

    for (int i = tid; i < 4096; i += 256) {
        int c = i >> 6, o = i & 63;
        wsT[c*64 + o] = pqw[blk*4096 + o*64 + c];
    }
    for (int i = tid; i < 1024; i += 256)
        swdw[i] = dww[blk*NCH*16 + i];
    if (tid < 64) {
        bs[tid]   = pqb[blk*64 + tid];
        sdwb[tid] = dwb[blk*64 + tid];
    }
    __syncthreads();

    int hw = tile*256 + tid;
    float* qout = g_Q + (size_t)bb * NCH * HWQ;

    float acc[64];
    #pragma unroll
    for (int o = 0; o < 64; ++o) acc[o] = bs[o];
    #pragma unroll 2
    for (int c = 0; c < 64; ++c) {
        float xv = __ldg(&xin[c*HWQ + hw]);
        const float4* wr = reinterpret_cast<const float4*>(&wsT[c*64]);
        #pragma unroll
        for (int o4 = 0; o4 < 16; ++o4) {
            float4 w = wr[o4];
            acc[o4*4+0] = fmaf(w.x, xv, acc[o4*4+0]);
            acc[o4*4+1] = fmaf(w.y, xv, acc[o4*4+1]);
            acc[o4*4+2] = fmaf(w.z, xv, acc[o4*4+2]);
            acc[o4*4+3] = fmaf(w.w, xv, acc[o4*4+3]);
        }
    }
    #pragma unroll
    for (int o = 0; o < 64; ++o) qout[o*HWQ + hw] = acc[o];

    // ---- fused depthwise conv: quarters of 16 channels through smem ----
    float* dwp = g_DW + (size_t)bb * NS * NCH;
    int cl = tid >> 4, ox = tid & 15;        // one output (c,ox) per thread
    #pragma unroll
    for (int q4 = 0; q4 < 4; ++q4) {
        __syncthreads();
        #pragma unroll
        for (int cc = 0; cc < 16; ++cc)
            sq[cc*256 + tid] = acc[q4*16 + cc];
        __syncthreads();
        int c = q4*16 + cl;
        float a = sdwb[c];
        const float* w = &swdw[c*16];
        const float* sp = sq + cl*256 + ox*4;
        #pragma unroll
        for (int ky = 0; ky < 4; ++ky)
            #pragma unroll
            for (int kx = 0; kx < 4; ++kx)
                a = fmaf(sp[ky*64 + kx], w[ky*4 + kx], a);
        dwp[(tile*16 + ox)*NCH + c] = a;
    }
}

// ============================================================================
// Kernel B2: LN -> GELU -> 1x1 -> offsets -> pos + bias params.
// g_DW is [n][c] -> contiguous float4 reads. grid = 24, 256 threads (1 per n)
// ============================================================================
__global__ __launch_bounds__(256) void k_off2(
    const float* __restrict__ lng, const float* __restrict__ lnb,
    const float* __restrict__ pww)
{
    int bx = blockIdx.x;
    int b = bx & 7, blk = bx >> 3;
    int n = threadIdx.x;
    int oy = n >> 4, ox = n & 15;
    const float4* dwp = reinterpret_cast<const float4*>(
        g_DW + ((size_t)(blk*BD + b)*NS + n) * NCH);

    float s1 = 0.f, s2 = 0.f;
    #pragma unroll
    for (int i = 0; i < 16; ++i) {
        float4 a = __ldg(&dwp[i]);
        s1 += a.x + a.y + a.z + a.w;
        s2 += a.x*a.x + a.y*a.y + a.z*a.z + a.w*a.w;
    }
    float mu  = s1 * (1.f/64.f);
    float var = s2 * (1.f/64.f) - mu*mu;
    float rs  = rsqrtf(var + 1e-5f);

    float offy = 0.f, offx = 0.f;
    #pragma unroll 4
    for (int i = 0; i < 16; ++i) {
        float4 a = __ldg(&dwp[i]);
        float av[4] = {a.x, a.y, a.z, a.w};
        #pragma unroll
        for (int k = 0; k < 4; ++k) {
            int c = i*4 + k;
            float t = (av[k] - mu) * rs * __ldg(&lng[blk*64 + c]) + __ldg(&lnb[blk*64 + c]);
            float gl = 0.5f * t * (1.f + erff(t * 0.70710678118654752f));
            offy = fmaf(__ldg(&pww[blk*128 + c]),      gl, offy);
            offx = fmaf(__ldg(&pww[blk*128 + 64 + c]), gl, offx);
        }
    }
    float refy = (2.f*((float)oy + 0.5f)) * (1.f/15.f) - 1.f;
    float refx = (2.f*((float)ox + 0.5f)) * (1.f/15.f) - 1.f;
    float py = fminf(fmaxf(offy + refy, -1.f), 1.f);
    float px = fminf(fmaxf(offx + refx, -1.f), 1.f);

    float ay = 31.5f*(1.f - py), ax = 31.5f*(1.f - px);
    float by0 = floorf(ay), bx0 = floorf(ax);
    g_BP[(blk*BD + b)*NS + n]  = make_float4(by0*127.f + bx0, ay - by0, ax - bx0, 0.f);
    g_POS[(blk*BD + b)*NS + n] = make_float2(py, px);
}

// ============================================================================
// Kernel B3: deformable gather + k/v projections.
// grid = 96 (3 blk * 8 b * 4 n-chunks of 64), 256 threads = (nl 64, cg 4)
// ============================================================================
__global__ __launch_bounds__(256) void k_gkv(
    const float* __restrict__ x0, const float* __restrict__ x1,
    const float* __restrict__ pkw, const float* __restrict__ pkb,
    const float* __restrict__ pvw, const float* __restrict__ pvb)
{
    extern __shared__ float sm[];
    float* buf = sm;              // [64][65]
    float* skw = sm + 64*65;      // 4096
    float* svw = skw + 4096;      // 4096

    int bx = blockIdx.x;
    int nc = bx & 3, b = (bx >> 2) & 7, blk = bx >> 5;
    const float* kvsrc = (blk == 2 ? x1 : x0) + (size_t)b * 128 * HWQ;
    int tid = threadIdx.x;
    int nl = tid & 63, cg = tid >> 6;
    int n = nc*64 + nl;

    for (int i = tid; i < 4096; i += 256) {
        skw[i] = pkw[blk*4096 + i];
        svw[i] = pvw[blk*4096 + i];
    }

    float2 pos = g_POS[(blk*BD + b)*NS + n];
    float sy = (pos.x + 1.f)*31.5f, sx = (pos.y + 1.f)*31.5f;
    float fy = floorf(sy), fx = floorf(sx);
    int iy0 = (int)fy, ix0 = (int)fx;
    float wby = sy - fy, wbx = sx - fx;
    int iy1 = min(iy0 + 1, 63), ix1 = min(ix0 + 1, 63);
    float w00 = (1.f-wby)*(1.f-wbx), w01 = (1.f-wby)*wbx;
    float w10 = wby*(1.f-wbx),       w11 = wby*wbx;
    #pragma unroll 4
    for (int cc = 0; cc < 16; ++cc) {
        int c = cg*16 + cc;
        const float* ip = kvsrc + c*HWQ;
        float val = w00*__ldg(&ip[iy0*64 + ix0]) + w01*__ldg(&ip[iy0*64 + ix1])
                  + w10*__ldg(&ip[iy1*64 + ix0]) + w11*__ldg(&ip[iy1*64 + ix1]);
        buf[nl*65 + c] = val;
    }
    __syncthreads();

    float* kout = g_K + (size_t)(blk*BD + b)*NCH*NS;
    float* vout = g_V + (size_t)(blk*BD + b)*NCH*NS;
    #pragma unroll 2
    for (int oo = 0; oo < 16; ++oo) {
        int o = cg*16 + oo;
        float ak = __ldg(&pkb[blk*64 + o]);
        float av = __ldg(&pvb[blk*64 + o]);
        #pragma unroll 8
        for (int c = 0; c < 64; ++c) {
            float xv = buf[nl*65 + c];
            ak = fmaf(skw[o*64 + c], xv, ak);
            av = fmaf(svw[o*64 + c], xv, av);
        }
        kout[o*NS + n] = ak;
        vout[o*NS + n] = av;
    }
}

// ============================================================================
// Kernel D: attention (R4 proven version). One CTA per (bb,head,row-tile of 8).
// 256 threads, each = vertical query PAIR (rows y,y+1, same column).
// ============================================================================
__global__ __launch_bounds__(256, 2) void k_attn()
{
    extern __shared__ float sm[];
    float*  Ks  = sm;                          // 256*16, [n][c]
    float*  Vs  = Ks + 4096;                   // 256*16
    float4* pp4 = (float4*)(Vs + 4096);        // 256: (w00,w01,w10, base)

    int bx = blockIdx.x;
    int tile = bx & 7, head = (bx >> 3) & 3, bb = bx >> 5;  // bb = blk*8+b
    int tid = threadIdx.x;

    const float2* tab = g_TAB2 + (size_t)((bb >> 3)*4 + head) * TABP;

    const float* kg = g_K + (size_t)(bb*NCH + head*HCD) * NS;
    const float* vg = g_V + (size_t)(bb*NCH + head*HCD) * NS;
    #pragma unroll
    for (int c4 = 0; c4 < 4; ++c4) {
        float a0 = kg[(c4*4+0)*NS + tid], a1 = kg[(c4*4+1)*NS + tid];
        float a2 = kg[(c4*4+2)*NS + tid], a3 = kg[(c4*4+3)*NS + tid];
        reinterpret_cast<float4*>(Ks)[tid*4 + c4] = make_float4(a0,a1,a2,a3);
        a0 = vg[(c4*4+0)*NS + tid]; a1 = vg[(c4*4+1)*NS + tid];
        a2 = vg[(c4*4+2)*NS + tid]; a3 = vg[(c4*4+3)*NS + tid];
        reinterpret_cast<float4*>(Vs)[tid*4 + c4] = make_float4(a0,a1,a2,a3);
    }
    {
        float4 bp = g_BP[bb*NS + tid];
        float wy = bp.y, wx = bp.z;
        pp4[tid] = make_float4((1.f-wy)*(1.f-wx), (1.f-wy)*wx, wy*(1.f-wx), bp.x);
    }
    __syncthreads();

    int x = tid & 63, yp = tid >> 6;
    int y = tile*8 + yp*2;
    int m1 = y*64 + x;                 // m2 = m1 + 64 (row y+1)
    int rbase = y*127 + x;
    const float* qg = g_Q + (size_t)(bb*NCH + head*HCD) * HWQ;
    float q1[16], q2[16];
    #pragma unroll
    for (int c = 0; c < 16; ++c) {
        q1[c] = qg[c*HWQ + m1];
        q2[c] = qg[c*HWQ + m1 + 64];
    }

    float acc1[16], acc2[16];
    #pragma unroll
    for (int c = 0; c < 16; ++c) { acc1[c] = 0.f; acc2[c] = 0.f; }
    float ss1 = 0.f, ss2 = 0.f;

    const float4* Ks4 = (const float4*)Ks;
    const float4* Vs4 = (const float4*)Vs;

    #pragma unroll 2
    for (int n = 0; n < 256; ++n) {
        float4 pp = pp4[n];
        int o = (int)pp.w + rbase;
        float w11 = 1.f - pp.x - pp.y - pp.z;
        float2 t0 = __ldg(&tab[o]);
        float2 t1 = __ldg(&tab[o + 127]);
        float2 t2 = __ldg(&tab[o + 254]);
        float b1 = pp.x * t0.x;
        b1 = fmaf(pp.y, t0.y, b1); b1 = fmaf(pp.z, t1.x, b1); b1 = fmaf(w11, t1.y, b1);
        float b2 = pp.x * t1.x;
        b2 = fmaf(pp.y, t1.y, b2); b2 = fmaf(pp.z, t2.x, b2); b2 = fmaf(w11, t2.y, b2);

        float4 k0 = Ks4[n*4+0], k1 = Ks4[n*4+1], k2 = Ks4[n*4+2], k3 = Ks4[n*4+3];
        float d1 = q1[0]*k0.x;
        d1 = fmaf(q1[1], k0.y, d1); d1 = fmaf(q1[2],  k0.z, d1); d1 = fmaf(q1[3],  k0.w, d1);
        d1 = fmaf(q1[4], k1.x, d1); d1 = fmaf(q1[5],  k1.y, d1); d1 = fmaf(q1[6],  k1.z, d1);
        d1 = fmaf(q1[7], k1.w, d1); d1 = fmaf(q1[8],  k2.x, d1); d1 = fmaf(q1[9],  k2.y, d1);
        d1 = fmaf(q1[10],k2.z, d1); d1 = fmaf(q1[11], k2.w, d1); d1 = fmaf(q1[12], k3.x, d1);
        d1 = fmaf(q1[13],k3.y, d1); d1 = fmaf(q1[14], k3.z, d1); d1 = fmaf(q1[15], k3.w, d1);
        float d2 = q2[0]*k0.x;
        d2 = fmaf(q2[1], k0.y, d2); d2 = fmaf(q2[2],  k0.z, d2); d2 = fmaf(q2[3],  k0.w, d2);
        d2 = fmaf(q2[4], k1.x, d2); d2 = fmaf(q2[5],  k1.y, d2); d2 = fmaf(q2[6],  k1.z, d2);
        d2 = fmaf(q2[7], k1.w, d2); d2 = fmaf(q2[8],  k2.x, d2); d2 = fmaf(q2[9],  k2.y, d2);
        d2 = fmaf(q2[10],k2.z, d2); d2 = fmaf(q2[11], k2.w, d2); d2 = fmaf(q2[12], k3.x, d2);
        d2 = fmaf(q2[13],k3.y, d2); d2 = fmaf(q2[14], k3.z, d2); d2 = fmaf(q2[15], k3.w, d2);

        float p1 = __expf(fmaf(d1, 0.25f, b1)); ss1 += p1;
        float p2 = __expf(fmaf(d2, 0.25f, b2)); ss2 += p2;

        float4 v0 = Vs4[n*4+0], v1 = Vs4[n*4+1], v2 = Vs4[n*4+2], v3 = Vs4[n*4+3];
        acc1[0]  = fmaf(p1, v0.x, acc1[0]);  acc2[0]  = fmaf(p2, v0.x, acc2[0]);
        acc1[1]  = fmaf(p1, v0.y, acc1[1]);  acc2[1]  = fmaf(p2, v0.y, acc2[1]);
        acc1[2]  = fmaf(p1, v0.z, acc1[2]);  acc2[2]  = fmaf(p2, v0.z, acc2[2]);
        acc1[3]  = fmaf(p1, v0.w, acc1[3]);  acc2[3]  = fmaf(p2, v0.w, acc2[3]);
        acc1[4]  = fmaf(p1, v1.x, acc1[4]);  acc2[4]  = fmaf(p2, v1.x, acc2[4]);
        acc1[5]  = fmaf(p1, v1.y, acc1[5]);  acc2[5]  = fmaf(p2, v1.y, acc2[5]);
        acc1[6]  = fmaf(p1, v1.z, acc1[6]);  acc2[6]  = fmaf(p2, v1.z, acc2[6]);
        acc1[7]  = fmaf(p1, v1.w, acc1[7]);  acc2[7]  = fmaf(p2, v1.w, acc2[7]);
        acc1[8]  = fmaf(p1, v2.x, acc1[8]);  acc2[8]  = fmaf(p2, v2.x, acc2[8]);
        acc1[9]  = fmaf(p1, v2.y, acc1[9]);  acc2[9]  = fmaf(p2, v2.y, acc2[9]);
        acc1[10] = fmaf(p1, v2.z, acc1[10]); acc2[10] = fmaf(p2, v2.z, acc2[10]);
        acc1[11] = fmaf(p1, v2.w, acc1[11]); acc2[11] = fmaf(p2, v2.w, acc2[11]);
        acc1[12] = fmaf(p1, v3.x, acc1[12]); acc2[12] = fmaf(p2, v3.x, acc2[12]);
        acc1[13] = fmaf(p1, v3.y, acc1[13]); acc2[13] = fmaf(p2, v3.y, acc2[13]);
        acc1[14] = fmaf(p1, v3.z, acc1[14]); acc2[14] = fmaf(p2, v3.z, acc2[14]);
        acc1[15] = fmaf(p1, v3.w, acc1[15]); acc2[15] = fmaf(p2, v3.w, acc2[15]);
    }

    float i1 = 1.f / ss1, i2 = 1.f / ss2;
    float* og = g_O + (size_t)(bb*NCH + head*HCD) * HWQ;
    #pragma unroll
    for (int c = 0; c < 16; ++c) {
        og[c*HWQ + m1]      = acc1[c] * i1;
        og[c*HWQ + m1 + 64] = acc2[c] * i2;
    }
}

// ============================================================================
// Kernel E: output projection + residual for channels 64..127, levels 1 & 2
// only (passthrough handled by memcpy nodes). grid = 256, 256 threads.
// ============================================================================
__global__ __launch_bounds__(256) void k_out(
    const float* __restrict__ x1, const float* __restrict__ x2,
    const float* __restrict__ poww, const float* __restrict__ pob,
    float* __restrict__ out)
{
    __shared__ float wsT[2][64*64];
    __shared__ float bsum[64];
    int bx = blockIdx.x;
    int tile = bx & 15, b = (bx >> 4) & 7, lvl = 1 + (bx >> 7);
    const float* xl = (lvl == 1 ? x1 : x2) + (size_t)b * 128 * HWQ;
    float* outp = out + (size_t)(lvl*BD + b) * 128 * HWQ;
    int hw = tile*256 + threadIdx.x;

    int blk0 = (lvl == 1) ? 0 : 1;
    int nb   = (lvl == 1) ? 1 : 2;

    for (int i = threadIdx.x; i < 4096; i += 256) {
        int c = i >> 6, o = i & 63;
        wsT[0][c*64 + o] = poww[blk0*4096 + o*64 + c];
        if (nb == 2) wsT[1][c*64 + o] = poww[(blk0+1)*4096 + o*64 + c];
    }
    if (threadIdx.x < 64) {
        float s = pob[blk0*64 + threadIdx.x];
        if (nb == 2) s += pob[(blk0+1)*64 + threadIdx.x];
        bsum[threadIdx.x] = s;
    }
    __syncthreads();

    const float* o0 = g_O + (size_t)(blk0*BD + b) * NCH * HWQ;
    const float* o1 = g_O + (size_t)((blk0+1)*BD + b) * NCH * HWQ;

    float acc[64];
    #pragma unroll
    for (int o = 0; o < 64; ++o)
        acc[o] = __ldg(&xl[(64 + o)*HWQ + hw]) + bsum[o];

    #pragma unroll 2
    for (int c = 0; c < 64; ++c) {
        float a0 = o0[c*HWQ + hw];
        const float4* wr = reinterpret_cast<const float4*>(&wsT[0][c*64]);
        #pragma unroll
        for (int o4 = 0; o4 < 16; ++o4) {
            float4 w = wr[o4];
            acc[o4*4+0] = fmaf(w.x, a0, acc[o4*4+0]);
            acc[o4*4+1] = fmaf(w.y, a0, acc[o4*4+1]);
            acc[o4*4+2] = fmaf(w.z, a0, acc[o4*4+2]);
            acc[o4*4+3] = fmaf(w.w, a0, acc[o4*4+3]);
        }
    }
    if (nb == 2) {
        #pragma unroll 2
        for (int c = 0; c < 64; ++c) {
            float a1 = o1[c*HWQ + hw];
            const float4* wr = reinterpret_cast<const float4*>(&wsT[1][c*64]);
            #pragma unroll
            for (int o4 = 0; o4 < 16; ++o4) {
                float4 w = wr[o4];
                acc[o4*4+0] = fmaf(w.x, a1, acc[o4*4+0]);
                acc[o4*4+1] = fmaf(w.y, a1, acc[o4*4+1]);
                acc[o4*4+2] = fmaf(w.z, a1, acc[o4*4+2]);
                acc[o4*4+3] = fmaf(w.w, a1, acc[o4*4+3]);
            }
        }
    }
    #pragma unroll
    for (int o = 0; o < 64; ++o)
        outp[(64 + o)*HWQ + hw] = acc[o];
}

// ============================================================================
extern "C" void kernel_launch(void* const* d_in, const int* in_sizes, int n_in,
                              void* d_out, int out_size)
{
    const float* x0  = (const float*)d_in[0];
    const float* x1  = (const float*)d_in[1];
    const float* x2  = (const float*)d_in[2];
    const float* pqw = (const float*)d_in[3];
    const float* pqb = (const float*)d_in[4];
    const float* dww = (const float*)d_in[5];
    const float* dwb = (const float*)d_in[6];
    const float* lng = (const float*)d_in[7];
    const float* lnb = (const float*)d_in[8];
    const float* pww = (const float*)d_in[9];
    const float* pkw = (const float*)d_in[10];
    const float* pkb = (const float*)d_in[11];
    const float* pvw = (const float*)d_in[12];
    const float* pvb = (const float*)d_in[13];
    const float* pow_ = (const float*)d_in[14];
    const float* pob = (const float*)d_in[15];
    const float* rpe = (const float*)d_in[16];
    float* out = (float*)d_out;

    const int gkv_smem = (64*65 + 4096 + 4096) * 4;        // 49408 B
    const int d_smem   = (4096 + 4096) * 4 + 256*16;       // 36864 B
    cudaFuncSetAttribute(k_gkv,  cudaFuncAttributeMaxDynamicSharedMemorySize, gkv_smem);
    cudaFuncSetAttribute(k_attn, cudaFuncAttributeMaxDynamicSharedMemorySize, d_smem);

    const size_t LVL = (size_t)BD * 128 * HWQ;             // floats per level
    const size_t BAT = (size_t)128 * HWQ;                  // floats per batch image

    // passthrough copies (independent of compute; graph memcpy nodes)
    cudaMemcpyAsync(out, x0, LVL * 4, cudaMemcpyDeviceToDevice);
    for (int b = 0; b < BD; ++b)
        cudaMemcpyAsync(out + LVL + b*BAT, x1 + b*BAT, (BAT/2) * 4,
                        cudaMemcpyDeviceToDevice);
    for (int b = 0; b < BD; ++b)
        cudaMemcpyAsync(out + 2*LVL + b*BAT, x2 + b*BAT, (BAT/2) * 4,
                        cudaMemcpyDeviceToDevice);

    k_tab2<<<96, 256>>>(rpe);
    k_qproj_dw<<<384, 256>>>(x1, x2, pqw, pqb, dww, dwb);
    k_off2<<<24, 256>>>(lng, lnb, pww);
    k_gkv<<<96, 256, gkv_smem>>>(x0, x1, pkw, pkb, pvw, pvb);
    k_attn<<<768, 256, d_smem>>>();
    k_out<<<256, 256>>>(x1, x2, pow_, pob, out);
}

// round 7
// speedup vs baseline: 1.1828x; 1.0415x over previous
#include <cuda_runtime.h>
#include <math.h>
#include <stdint.h>

#define NBLK 3
#define BD 8
#define HWQ 4096   // 64*64
#define NCH 64     // NC (channels per DAT block)
#define NS  256    // Hk*Wk = 16*16
#define HCD 16     // head channels
#define TABN 16129 // 127*127
#define TABP 16384 // padded dual-table stride

// ---- static device scratch (no runtime allocation allowed) ----
__device__ float  g_Q[NBLK*BD*NCH*HWQ];   // q projections      [blk][b][c][hw]
__device__ float  g_O[NBLK*BD*NCH*HWQ];   // attention outputs  [blk][b][c][hw]
__device__ float  g_K[NBLK*BD*NCH*NS];    // keys   [blk][b][c][n]
__device__ float  g_V[NBLK*BD*NCH*NS];    // values [blk][b][c][n]
__device__ float4 g_BP[NBLK*BD*NS];       // bias params per n: (y0*127+x0, wy, wx, 0)
__device__ float2 g_POS[NBLK*BD*NS];      // normalized sample pos (py,px)
__device__ float  g_DW[NBLK*BD*NS*NCH];   // dwconv output [bb][n][c]  (c contiguous)
__device__ float2 g_TAB2[NBLK*4*TABP];    // dual RPE tables: (t[i], t[i+1]), zero-padded

// ---- packed f32x2 helpers (Blackwell sm_103a) ----
typedef unsigned long long u64t;
__device__ __forceinline__ u64t pk2(float a, float b) {
    u64t r; asm("mov.b64 %0, {%1, %2};" : "=l"(r) : "f"(a), "f"(b)); return r;
}
__device__ __forceinline__ float2 upk2(u64t v) {
    float x, y; asm("mov.b64 {%0, %1}, %2;" : "=f"(x), "=f"(y) : "l"(v));
    return make_float2(x, y);
}
__device__ __forceinline__ u64t fma2(u64t a, u64t b, u64t c) {
    u64t r; asm("fma.rn.f32x2 %0, %1, %2, %3;" : "=l"(r) : "l"(a), "l"(b), "l"(c));
    return r;
}
__device__ __forceinline__ u64t mul2(u64t a, u64t b) {
    u64t r; asm("mul.rn.f32x2 %0, %1, %2;" : "=l"(r) : "l"(a), "l"(b));
    return r;
}

// ============================================================================
// Kernel T: build dual tables. grid = 12 tables * 8 chunks = 96
// ============================================================================
__global__ __launch_bounds__(256) void k_tab2(const float* __restrict__ rpe)
{
    int t = blockIdx.x >> 3, q = blockIdx.x & 7;
    const float* src = rpe + (size_t)t * TABN;
    float2* dst = g_TAB2 + (size_t)t * TABP;
    #pragma unroll
    for (int k = 0; k < 8; ++k) {
        int i = q*2048 + k*256 + threadIdx.x;
        float a = (i < TABN)     ? src[i]   : 0.f;
        float b = (i+1 < TABN)   ? src[i+1] : 0.f;
        dst[i] = make_float2(a, b);
    }
}

// ============================================================================
// Kernel A: q-projection FUSED with depthwise conv 4x4 s4.
// grid = 384 (3 blk * 8 b * 16 tiles of 256 hw = 4 image rows), 256 threads.
// ============================================================================
__global__ __launch_bounds__(256) void k_qproj_dw(
    const float* __restrict__ x1, const float* __restrict__ x2,
    const float* __restrict__ pqw, const float* __restrict__ pqb,
    const float* __restrict__ dww, const float* __restrict__ dwb)
{
    __shared__ float wsT[64*64];
    __shared__ float bs[64];
    __shared__ float sq[16*256];
    __shared__ float swdw[64*16];
    __shared__ float sdwb[64];

    int bx = blockIdx.x;
    int tile = bx & 15, b = (bx >> 4) & 7, blk = bx >> 7;
    int bb = blk*BD + b;
    const float* xin = (blk == 0 ? x1 : x2) + (size_t)b * 128 * HWQ;
    int tid = threadIdx.x;

    for (int i = tid; i < 4096; i += 256) {
        int c = i >> 6, o = i & 63;
        wsT[c*64 + o] = pqw[blk*4096 + o*64 + c];
    }
    for (int i = tid; i < 1024; i += 256)
        swdw[i] = dww[blk*NCH*16 + i];
    if (tid < 64) {
        bs[tid]   = pqb[blk*64 + tid];
        sdwb[tid] = dwb[blk*64 + tid];
    }
    __syncthreads();

    int hw = tile*256 + tid;
    float* qout = g_Q + (size_t)bb * NCH * HWQ;

    float acc[64];
    #pragma unroll
    for (int o = 0; o < 64; ++o) acc[o] = bs[o];
    #pragma unroll 2
    for (int c = 0; c < 64; ++c) {
        float xv = __ldg(&xin[c*HWQ + hw]);
        const float4* wr = reinterpret_cast<const float4*>(&wsT[c*64]);
        #pragma unroll
        for (int o4 = 0; o4 < 16; ++o4) {
            float4 w = wr[o4];
            acc[o4*4+0] = fmaf(w.x, xv, acc[o4*4+0]);
            acc[o4*4+1] = fmaf(w.y, xv, acc[o4*4+1]);
            acc[o4*4+2] = fmaf(w.z, xv, acc[o4*4+2]);
            acc[o4*4+3] = fmaf(w.w, xv, acc[o4*4+3]);
        }
    }
    #pragma unroll
    for (int o = 0; o < 64; ++o) qout[o*HWQ + hw] = acc[o];

    // ---- fused depthwise conv: quarters of 16 channels through smem ----
    float* dwp = g_DW + (size_t)bb * NS * NCH;
    int cl = tid >> 4, ox = tid & 15;
    #pragma unroll
    for (int q4 = 0; q4 < 4; ++q4) {
        __syncthreads();
        #pragma unroll
        for (int cc = 0; cc < 16; ++cc)
            sq[cc*256 + tid] = acc[q4*16 + cc];
        __syncthreads();
        int c = q4*16 + cl;
        float a = sdwb[c];
        const float* w = &swdw[c*16];
        const float* sp = sq + cl*256 + ox*4;
        #pragma unroll
        for (int ky = 0; ky < 4; ++ky)
            #pragma unroll
            for (int kx = 0; kx < 4; ++kx)
                a = fmaf(sp[ky*64 + kx], w[ky*4 + kx], a);
        dwp[(tile*16 + ox)*NCH + c] = a;
    }
}

// ============================================================================
// Kernel B2: LN -> GELU -> 1x1 -> offsets -> pos + bias params.
// grid = 24, 256 threads (1 per n); g_DW [n][c] -> contiguous float4 reads.
// ============================================================================
__global__ __launch_bounds__(256) void k_off2(
    const float* __restrict__ lng, const float* __restrict__ lnb,
    const float* __restrict__ pww)
{
    int bx = blockIdx.x;
    int b = bx & 7, blk = bx >> 3;
    int n = threadIdx.x;
    int oy = n >> 4, ox = n & 15;
    const float4* dwp = reinterpret_cast<const float4*>(
        g_DW + ((size_t)(blk*BD + b)*NS + n) * NCH);

    float s1 = 0.f, s2 = 0.f;
    #pragma unroll
    for (int i = 0; i < 16; ++i) {
        float4 a = __ldg(&dwp[i]);
        s1 += a.x + a.y + a.z + a.w;
        s2 += a.x*a.x + a.y*a.y + a.z*a.z + a.w*a.w;
    }
    float mu  = s1 * (1.f/64.f);
    float var = s2 * (1.f/64.f) - mu*mu;
    float rs  = rsqrtf(var + 1e-5f);

    float offy = 0.f, offx = 0.f;
    #pragma unroll 4
    for (int i = 0; i < 16; ++i) {
        float4 a = __ldg(&dwp[i]);
        float av[4] = {a.x, a.y, a.z, a.w};
        #pragma unroll
        for (int k = 0; k < 4; ++k) {
            int c = i*4 + k;
            float t = (av[k] - mu) * rs * __ldg(&lng[blk*64 + c]) + __ldg(&lnb[blk*64 + c]);
            float gl = 0.5f * t * (1.f + erff(t * 0.70710678118654752f));
            offy = fmaf(__ldg(&pww[blk*128 + c]),      gl, offy);
            offx = fmaf(__ldg(&pww[blk*128 + 64 + c]), gl, offx);
        }
    }
    float refy = (2.f*((float)oy + 0.5f)) * (1.f/15.f) - 1.f;
    float refx = (2.f*((float)ox + 0.5f)) * (1.f/15.f) - 1.f;
    float py = fminf(fmaxf(offy + refy, -1.f), 1.f);
    float px = fminf(fmaxf(offx + refx, -1.f), 1.f);

    float ay = 31.5f*(1.f - py), ax = 31.5f*(1.f - px);
    float by0 = floorf(ay), bx0 = floorf(ax);
    g_BP[(blk*BD + b)*NS + n]  = make_float4(by0*127.f + bx0, ay - by0, ax - bx0, 0.f);
    g_POS[(blk*BD + b)*NS + n] = make_float2(py, px);
}

// ============================================================================
// Kernel B3: deformable gather + k/v projections.
// grid = 192 (3 blk * 8 b * 8 n-chunks of 32), 256 threads = (nl 32, cg 8).
// Weights stored TRANSPOSED in smem -> broadcast LDS.128 in GEMV inner loop.
// ============================================================================
__global__ __launch_bounds__(256) void k_gkv(
    const float* __restrict__ x0, const float* __restrict__ x1,
    const float* __restrict__ pkw, const float* __restrict__ pkb,
    const float* __restrict__ pvw, const float* __restrict__ pvb)
{
    extern __shared__ float sm[];
    float* buf  = sm;               // [32][65]
    float* skwT = sm + 32*65;       // [c][o] 4096
    float* svwT = skwT + 4096;      // 4096

    int bx = blockIdx.x;
    int chunk = bx & 7, b = (bx >> 3) & 7, blk = bx >> 6;
    const float* kvsrc = (blk == 2 ? x1 : x0) + (size_t)b * 128 * HWQ;
    int tid = threadIdx.x;
    int nl = tid & 31, cg = tid >> 5;      // warp == one cg -> weight broadcast
    int n = chunk*32 + nl;

    for (int i = tid; i < 4096; i += 256) {
        int o = i >> 6, c = i & 63;
        skwT[c*64 + o] = pkw[blk*4096 + i];
        svwT[c*64 + o] = pvw[blk*4096 + i];
    }

    float2 pos = g_POS[(blk*BD + b)*NS + n];
    float sy = (pos.x + 1.f)*31.5f, sx = (pos.y + 1.f)*31.5f;
    float fy = floorf(sy), fx = floorf(sx);
    int iy0 = (int)fy, ix0 = (int)fx;
    float wby = sy - fy, wbx = sx - fx;
    int iy1 = min(iy0 + 1, 63), ix1 = min(ix0 + 1, 63);
    float w00 = (1.f-wby)*(1.f-wbx), w01 = (1.f-wby)*wbx;
    float w10 = wby*(1.f-wbx),       w11 = wby*wbx;
    #pragma unroll 4
    for (int cc = 0; cc < 8; ++cc) {
        int c = cg*8 + cc;
        const float* ip = kvsrc + c*HWQ;
        float val = w00*__ldg(&ip[iy0*64 + ix0]) + w01*__ldg(&ip[iy0*64 + ix1])
                  + w10*__ldg(&ip[iy1*64 + ix0]) + w11*__ldg(&ip[iy1*64 + ix1]);
        buf[nl*65 + c] = val;
    }
    __syncthreads();

    float ak[8], av[8];
    #pragma unroll
    for (int oo = 0; oo < 8; ++oo) {
        ak[oo] = __ldg(&pkb[blk*64 + cg*8 + oo]);
        av[oo] = __ldg(&pvb[blk*64 + cg*8 + oo]);
    }
    #pragma unroll 4
    for (int c = 0; c < 64; ++c) {
        float xv = buf[nl*65 + c];
        const float4* kwr = reinterpret_cast<const float4*>(&skwT[c*64 + cg*8]);
        const float4* vwr = reinterpret_cast<const float4*>(&svwT[c*64 + cg*8]);
        float4 k0 = kwr[0], k1 = kwr[1];
        float4 v0 = vwr[0], v1 = vwr[1];
        ak[0] = fmaf(k0.x, xv, ak[0]); ak[1] = fmaf(k0.y, xv, ak[1]);
        ak[2] = fmaf(k0.z, xv, ak[2]); ak[3] = fmaf(k0.w, xv, ak[3]);
        ak[4] = fmaf(k1.x, xv, ak[4]); ak[5] = fmaf(k1.y, xv, ak[5]);
        ak[6] = fmaf(k1.z, xv, ak[6]); ak[7] = fmaf(k1.w, xv, ak[7]);
        av[0] = fmaf(v0.x, xv, av[0]); av[1] = fmaf(v0.y, xv, av[1]);
        av[2] = fmaf(v0.z, xv, av[2]); av[3] = fmaf(v0.w, xv, av[3]);
        av[4] = fmaf(v1.x, xv, av[4]); av[5] = fmaf(v1.y, xv, av[5]);
        av[6] = fmaf(v1.z, xv, av[6]); av[7] = fmaf(v1.w, xv, av[7]);
    }

    float* kout = g_K + (size_t)(blk*BD + b)*NCH*NS;
    float* vout = g_V + (size_t)(blk*BD + b)*NCH*NS;
    #pragma unroll
    for (int oo = 0; oo < 8; ++oo) {
        int o = cg*8 + oo;
        kout[o*NS + n] = ak[oo];
        vout[o*NS + n] = av[oo];
    }
}

// ============================================================================
// Kernel D: attention with packed f32x2 math (full fp32 precision).
// One CTA per (bb,head,row-tile of 8). 256 threads, each = vertical query
// PAIR (rows y,y+1). Packing along channels: QK/PV use fma.rn.f32x2.
// smem: Ks[256][16], Vs[256][16], ppw[256] (wA,wB pairs), pbase[256].
// ============================================================================
__global__ __launch_bounds__(256, 2) void k_attn()
{
    extern __shared__ float sm[];
    float*      Ks    = sm;                            // 4096 floats
    float*      Vs    = sm + 4096;                     // 4096 floats
    ulonglong2* ppw   = (ulonglong2*)(sm + 8192);      // 256 * 16B
    int*        pbase = (int*)(sm + 8192 + 1024);      // 256

    int bx = blockIdx.x;
    int tile = bx & 7, head = (bx >> 3) & 3, bb = bx >> 5;  // bb = blk*8+b
    int tid = threadIdx.x;

    const u64t* tab = (const u64t*)(g_TAB2 + (size_t)((bb >> 3)*4 + head) * TABP);

    const float* kg = g_K + (size_t)(bb*NCH + head*HCD) * NS;
    const float* vg = g_V + (size_t)(bb*NCH + head*HCD) * NS;
    #pragma unroll
    for (int c4 = 0; c4 < 4; ++c4) {
        float a0 = kg[(c4*4+0)*NS + tid], a1 = kg[(c4*4+1)*NS + tid];
        float a2 = kg[(c4*4+2)*NS + tid], a3 = kg[(c4*4+3)*NS + tid];
        reinterpret_cast<float4*>(Ks)[tid*4 + c4] = make_float4(a0,a1,a2,a3);
        a0 = vg[(c4*4+0)*NS + tid]; a1 = vg[(c4*4+1)*NS + tid];
        a2 = vg[(c4*4+2)*NS + tid]; a3 = vg[(c4*4+3)*NS + tid];
        reinterpret_cast<float4*>(Vs)[tid*4 + c4] = make_float4(a0,a1,a2,a3);
    }
    {
        float4 bp = g_BP[bb*NS + tid];
        float wy = bp.y, wx = bp.z;
        ulonglong2 w;
        w.x = pk2((1.f-wy)*(1.f-wx), (1.f-wy)*wx);   // (w00, w01)
        w.y = pk2(wy*(1.f-wx),       wy*wx);         // (w10, w11)
        ppw[tid] = w;
        pbase[tid] = (int)bp.x;
    }
    __syncthreads();

    int x = tid & 63, yp = tid >> 6;
    int y = tile*8 + yp*2;
    int m1 = y*64 + x;
    int rbase = y*127 + x;
    const float* qg = g_Q + (size_t)(bb*NCH + head*HCD) * HWQ;
    u64t q1p[8], q2p[8];
    #pragma unroll
    for (int j = 0; j < 8; ++j) {
        q1p[j] = pk2(qg[(2*j)*HWQ + m1],      qg[(2*j+1)*HWQ + m1]);
        q2p[j] = pk2(qg[(2*j)*HWQ + m1 + 64], qg[(2*j+1)*HWQ + m1 + 64]);
    }

    u64t acc1p[8], acc2p[8];
    u64t zero = pk2(0.f, 0.f);
    #pragma unroll
    for (int j = 0; j < 8; ++j) { acc1p[j] = zero; acc2p[j] = zero; }
    float ss1 = 0.f, ss2 = 0.f;

    const ulonglong2* Ksu = (const ulonglong2*)Ks;
    const ulonglong2* Vsu = (const ulonglong2*)Vs;

    #pragma unroll 2
    for (int n = 0; n < 256; ++n) {
        ulonglong2 wp = ppw[n];
        int o = pbase[n] + rbase;
        u64t t0 = __ldg(&tab[o]);
        u64t t1 = __ldg(&tab[o + 127]);
        u64t t2 = __ldg(&tab[o + 254]);
        u64t b1p = fma2(wp.y, t1, mul2(wp.x, t0));
        u64t b2p = fma2(wp.y, t2, mul2(wp.x, t1));
        float2 b1u = upk2(b1p), b2u = upk2(b2p);
        float b1 = b1u.x + b1u.y, b2 = b2u.x + b2u.y;

        ulonglong2 kA = Ksu[n*4+0], kB = Ksu[n*4+1], kC = Ksu[n*4+2], kD = Ksu[n*4+3];
        u64t d1p = mul2(q1p[0], kA.x);
        d1p = fma2(q1p[1], kA.y, d1p); d1p = fma2(q1p[2], kB.x, d1p);
        d1p = fma2(q1p[3], kB.y, d1p); d1p = fma2(q1p[4], kC.x, d1p);
        d1p = fma2(q1p[5], kC.y, d1p); d1p = fma2(q1p[6], kD.x, d1p);
        d1p = fma2(q1p[7], kD.y, d1p);
        u64t d2p = mul2(q2p[0], kA.x);
        d2p = fma2(q2p[1], kA.y, d2p); d2p = fma2(q2p[2], kB.x, d2p);
        d2p = fma2(q2p[3], kB.y, d2p); d2p = fma2(q2p[4], kC.x, d2p);
        d2p = fma2(q2p[5], kC.y, d2p); d2p = fma2(q2p[6], kD.x, d2p);
        d2p = fma2(q2p[7], kD.y, d2p);
        float2 d1u = upk2(d1p), d2u = upk2(d2p);
        float d1 = d1u.x + d1u.y, d2 = d2u.x + d2u.y;

        float p1 = __expf(fmaf(d1, 0.25f, b1)); ss1 += p1;
        float p2 = __expf(fmaf(d2, 0.25f, b2)); ss2 += p2;
        u64t p1p = pk2(p1, p1), p2p = pk2(p2, p2);

        ulonglong2 vA = Vsu[n*4+0], vB = Vsu[n*4+1], vC = Vsu[n*4+2], vD = Vsu[n*4+3];
        acc1p[0] = fma2(p1p, vA.x, acc1p[0]); acc2p[0] = fma2(p2p, vA.x, acc2p[0]);
        acc1p[1] = fma2(p1p, vA.y, acc1p[1]); acc2p[1] = fma2(p2p, vA.y, acc2p[1]);
        acc1p[2] = fma2(p1p, vB.x, acc1p[2]); acc2p[2] = fma2(p2p, vB.x, acc2p[2]);
        acc1p[3] = fma2(p1p, vB.y, acc1p[3]); acc2p[3] = fma2(p2p, vB.y, acc2p[3]);
        acc1p[4] = fma2(p1p, vC.x, acc1p[4]); acc2p[4] = fma2(p2p, vC.x, acc2p[4]);
        acc1p[5] = fma2(p1p, vC.y, acc1p[5]); acc2p[5] = fma2(p2p, vC.y, acc2p[5]);
        acc1p[6] = fma2(p1p, vD.x, acc1p[6]); acc2p[6] = fma2(p2p, vD.x, acc2p[6]);
        acc1p[7] = fma2(p1p, vD.y, acc1p[7]); acc2p[7] = fma2(p2p, vD.y, acc2p[7]);
    }

    float i1 = 1.f / ss1, i2 = 1.f / ss2;
    float* og = g_O + (size_t)(bb*NCH + head*HCD) * HWQ;
    #pragma unroll
    for (int j = 0; j < 8; ++j) {
        float2 a1 = upk2(acc1p[j]), a2 = upk2(acc2p[j]);
        og[(2*j  )*HWQ + m1]      = a1.x * i1;
        og[(2*j+1)*HWQ + m1]      = a1.y * i1;
        og[(2*j  )*HWQ + m1 + 64] = a2.x * i2;
        og[(2*j+1)*HWQ + m1 + 64] = a2.y * i2;
    }
}

// ============================================================================
// Kernel E: output projection + residual for channels 64..127, levels 1 & 2
// only (passthrough handled by memcpy nodes). grid = 256, 256 threads.
// ============================================================================
__global__ __launch_bounds__(256) void k_out(
    const float* __restrict__ x1, const float* __restrict__ x2,
    const float* __restrict__ poww, const float* __restrict__ pob,
    float* __restrict__ out)
{
    __shared__ float wsT[2][64*64];
    __shared__ float bsum[64];
    int bx = blockIdx.x;
    int tile = bx & 15, b = (bx >> 4) & 7, lvl = 1 + (bx >> 7);
    const float* xl = (lvl == 1 ? x1 : x2) + (size_t)b * 128 * HWQ;
    float* outp = out + (size_t)(lvl*BD + b) * 128 * HWQ;
    int hw = tile*256 + threadIdx.x;

    int blk0 = (lvl == 1) ? 0 : 1;
    int nb   = (lvl == 1) ? 1 : 2;

    for (int i = threadIdx.x; i < 4096; i += 256) {
        int c = i >> 6, o = i & 63;
        wsT[0][c*64 + o] = poww[blk0*4096 + o*64 + c];
        if (nb == 2) wsT[1][c*64 + o] = poww[(blk0+1)*4096 + o*64 + c];
    }
    if (threadIdx.x < 64) {
        float s = pob[blk0*64 + threadIdx.x];
        if (nb == 2) s += pob[(blk0+1)*64 + threadIdx.x];
        bsum[threadIdx.x] = s;
    }
    __syncthreads();

    const float* o0 = g_O + (size_t)(blk0*BD + b) * NCH * HWQ;
    const float* o1 = g_O + (size_t)((blk0+1)*BD + b) * NCH * HWQ;

    float acc[64];
    #pragma unroll
    for (int o = 0; o < 64; ++o)
        acc[o] = __ldg(&xl[(64 + o)*HWQ + hw]) + bsum[o];

    #pragma unroll 2
    for (int c = 0; c < 64; ++c) {
        float a0 = o0[c*HWQ + hw];
        const float4* wr = reinterpret_cast<const float4*>(&wsT[0][c*64]);
        #pragma unroll
        for (int o4 = 0; o4 < 16; ++o4) {
            float4 w = wr[o4];
            acc[o4*4+0] = fmaf(w.x, a0, acc[o4*4+0]);
            acc[o4*4+1] = fmaf(w.y, a0, acc[o4*4+1]);
            acc[o4*4+2] = fmaf(w.z, a0, acc[o4*4+2]);
            acc[o4*4+3] = fmaf(w.w, a0, acc[o4*4+3]);
        }
    }
    if (nb == 2) {
        #pragma unroll 2
        for (int c = 0; c < 64; ++c) {
            float a1 = o1[c*HWQ + hw];
            const float4* wr = reinterpret_cast<const float4*>(&wsT[1][c*64]);
            #pragma unroll
            for (int o4 = 0; o4 < 16; ++o4) {
                float4 w = wr[o4];
                acc[o4*4+0] = fmaf(w.x, a1, acc[o4*4+0]);
                acc[o4*4+1] = fmaf(w.y, a1, acc[o4*4+1]);
                acc[o4*4+2] = fmaf(w.z, a1, acc[o4*4+2]);
                acc[o4*4+3] = fmaf(w.w, a1, acc[o4*4+3]);
            }
        }
    }
    #pragma unroll
    for (int o = 0; o < 64; ++o)
        outp[(64 + o)*HWQ + hw] = acc[o];
}

// ============================================================================
extern "C" void kernel_launch(void* const* d_in, const int* in_sizes, int n_in,
                              void* d_out, int out_size)
{
    const float* x0  = (const float*)d_in[0];
    const float* x1  = (const float*)d_in[1];
    const float* x2  = (const float*)d_in[2];
    const float* pqw = (const float*)d_in[3];
    const float* pqb = (const float*)d_in[4];
    const float* dww = (const float*)d_in[5];
    const float* dwb = (const float*)d_in[6];
    const float* lng = (const float*)d_in[7];
    const float* lnb = (const float*)d_in[8];
    const float* pww = (const float*)d_in[9];
    const float* pkw = (const float*)d_in[10];
    const float* pkb = (const float*)d_in[11];
    const float* pvw = (const float*)d_in[12];
    const float* pvb = (const float*)d_in[13];
    const float* pow_ = (const float*)d_in[14];
    const float* pob = (const float*)d_in[15];
    const float* rpe = (const float*)d_in[16];
    float* out = (float*)d_out;

    const int gkv_smem = (32*65 + 4096 + 4096) * 4;            // 41088 B
    const int d_smem   = 8192*4 + 256*16 + 256*4;              // 37888 B
    cudaFuncSetAttribute(k_gkv,  cudaFuncAttributeMaxDynamicSharedMemorySize, gkv_smem);
    cudaFuncSetAttribute(k_attn, cudaFuncAttributeMaxDynamicSharedMemorySize, d_smem);

    const size_t LVL = (size_t)BD * 128 * HWQ;
    const size_t BAT = (size_t)128 * HWQ;

    cudaMemcpyAsync(out, x0, LVL * 4, cudaMemcpyDeviceToDevice);
    for (int b = 0; b < BD; ++b)
        cudaMemcpyAsync(out + LVL + b*BAT, x1 + b*BAT, (BAT/2) * 4,
                        cudaMemcpyDeviceToDevice);
    for (int b = 0; b < BD; ++b)
        cudaMemcpyAsync(out + 2*LVL + b*BAT, x2 + b*BAT, (BAT/2) * 4,
                        cudaMemcpyDeviceToDevice);

    k_tab2<<<96, 256>>>(rpe);
    k_qproj_dw<<<384, 256>>>(x1, x2, pqw, pqb, dww, dwb);
    k_off2<<<24, 256>>>(lng, lnb, pww);
    k_gkv<<<192, 256, gkv_smem>>>(x0, x1, pkw, pkb, pvw, pvb);
    k_attn<<<768, 256, d_smem>>>();
    k_out<<<256, 256>>>(x1, x2, pow_, pob, out);
}

// round 8
// speedup vs baseline: 1.2101x; 1.0230x over previous
#include <cuda_runtime.h>
#include <math.h>
#include <stdint.h>

#define NBLK 3
#define BD 8
#define HWQ 4096   // 64*64
#define NCH 64     // NC (channels per DAT block)
#define NS  256    // Hk*Wk = 16*16
#define HCD 16     // head channels
#define TABN 16129 // 127*127
#define TABP 16384 // padded dual-table stride

// ---- static device scratch (no runtime allocation allowed) ----
__device__ float  g_Q[NBLK*BD*NCH*HWQ];   // q projections      [blk][b][c][hw]
__device__ float  g_O[NBLK*BD*NCH*HWQ];   // attention outputs  [blk][b][c][hw]
__device__ float  g_K[NBLK*BD*NCH*NS];    // keys   [blk][b][c][n]
__device__ float  g_V[NBLK*BD*NCH*NS];    // values [blk][b][c][n]
__device__ float4 g_BP[NBLK*BD*NS];       // bias params per n: (y0*127+x0, wy, wx, 0)
__device__ float2 g_POS[NBLK*BD*NS];      // normalized sample pos (py,px)
__device__ float2 g_TAB2[NBLK*4*TABP];    // dual RPE tables: (t[i], t[i+1]), zero-padded

// ---- packed f32x2 helpers (Blackwell sm_103a) ----
typedef unsigned long long u64t;
__device__ __forceinline__ u64t pk2(float a, float b) {
    u64t r; asm("mov.b64 %0, {%1, %2};" : "=l"(r) : "f"(a), "f"(b)); return r;
}
__device__ __forceinline__ float2 upk2(u64t v) {
    float x, y; asm("mov.b64 {%0, %1}, %2;" : "=f"(x), "=f"(y) : "l"(v));
    return make_float2(x, y);
}
__device__ __forceinline__ u64t fma2(u64t a, u64t b, u64t c) {
    u64t r; asm("fma.rn.f32x2 %0, %1, %2, %3;" : "=l"(r) : "l"(a), "l"(b), "l"(c));
    return r;
}
__device__ __forceinline__ u64t mul2(u64t a, u64t b) {
    u64t r; asm("mul.rn.f32x2 %0, %1, %2;" : "=l"(r) : "l"(a), "l"(b));
    return r;
}

// ============================================================================
// Kernel T: build dual tables. grid = 12 tables * 8 chunks = 96
// ============================================================================
__global__ __launch_bounds__(256) void k_tab2(const float* __restrict__ rpe)
{
    int t = blockIdx.x >> 3, q = blockIdx.x & 7;
    const float* src = rpe + (size_t)t * TABN;
    float2* dst = g_TAB2 + (size_t)t * TABP;
    #pragma unroll
    for (int k = 0; k < 8; ++k) {
        int i = q*2048 + k*256 + threadIdx.x;
        float a = (i < TABN)     ? src[i]   : 0.f;
        float b = (i+1 < TABN)   ? src[i+1] : 0.f;
        dst[i] = make_float2(a, b);
    }
}

// ============================================================================
// Kernel A: q-projection + depthwise conv 4x4 s4 + LN/GELU/offset head, all
// fused. grid = 384 (3 blk * 8 b * 16 tiles of 4 image rows), 256 threads.
// A tile holds one dwconv output row (16 n) across all 64 channels -> the
// offset head runs entirely in smem (half-warp shuffle reductions).
// ============================================================================
__global__ __launch_bounds__(256) void k_qproj_dw(
    const float* __restrict__ x1, const float* __restrict__ x2,
    const float* __restrict__ pqw, const float* __restrict__ pqb,
    const float* __restrict__ dww, const float* __restrict__ dwb,
    const float* __restrict__ lng, const float* __restrict__ lnb,
    const float* __restrict__ pww)
{
    __shared__ float wsT[64*64];   // 16 KB
    __shared__ float bs[64];
    __shared__ float sq[16*256];   // 16 KB  one 16-channel quarter of the q tile
    __shared__ float swdw[64*16];  // 4 KB
    __shared__ float sdwb[64];
    __shared__ float sdw[16*69];   // dwconv row: [local n][c], pad 69

    int bx = blockIdx.x;
    int tile = bx & 15, b = (bx >> 4) & 7, blk = bx >> 7;
    int bb = blk*BD + b;
    const float* xin = (blk == 0 ? x1 : x2) + (size_t)b * 128 * HWQ;
    int tid = threadIdx.x;

    for (int i = tid; i < 4096; i += 256) {
        int c = i >> 6, o = i & 63;
        wsT[c*64 + o] = pqw[blk*4096 + o*64 + c];
    }
    for (int i = tid; i < 1024; i += 256)
        swdw[i] = dww[blk*NCH*16 + i];
    if (tid < 64) {
        bs[tid]   = pqb[blk*64 + tid];
        sdwb[tid] = dwb[blk*64 + tid];
    }
    __syncthreads();

    int hw = tile*256 + tid;
    float* qout = g_Q + (size_t)bb * NCH * HWQ;

    float acc[64];
    #pragma unroll
    for (int o = 0; o < 64; ++o) acc[o] = bs[o];
    #pragma unroll 2
    for (int c = 0; c < 64; ++c) {
        float xv = __ldg(&xin[c*HWQ + hw]);
        const float4* wr = reinterpret_cast<const float4*>(&wsT[c*64]);
        #pragma unroll
        for (int o4 = 0; o4 < 16; ++o4) {
            float4 w = wr[o4];
            acc[o4*4+0] = fmaf(w.x, xv, acc[o4*4+0]);
            acc[o4*4+1] = fmaf(w.y, xv, acc[o4*4+1]);
            acc[o4*4+2] = fmaf(w.z, xv, acc[o4*4+2]);
            acc[o4*4+3] = fmaf(w.w, xv, acc[o4*4+3]);
        }
    }
    #pragma unroll
    for (int o = 0; o < 64; ++o) qout[o*HWQ + hw] = acc[o];

    // ---- fused depthwise conv: quarters of 16 channels through smem ----
    int cl = tid >> 4, ox = tid & 15;
    #pragma unroll
    for (int q4 = 0; q4 < 4; ++q4) {
        __syncthreads();
        #pragma unroll
        for (int cc = 0; cc < 16; ++cc)
            sq[cc*256 + tid] = acc[q4*16 + cc];
        __syncthreads();
        int c = q4*16 + cl;
        float a = sdwb[c];
        const float* w = &swdw[c*16];
        const float* sp = sq + cl*256 + ox*4;
        #pragma unroll
        for (int ky = 0; ky < 4; ++ky)
            #pragma unroll
            for (int kx = 0; kx < 4; ++kx)
                a = fmaf(sp[ky*64 + kx], w[ky*4 + kx], a);
        sdw[ox*69 + c] = a;
    }
    __syncthreads();

    // ---- fused offset head: LN -> GELU -> 1x1 -> pos + bias params ----
    // 8 warps, half-warp per local n (16 n), 4 channels per lane.
    {
        int warp = tid >> 5, lane = tid & 31;
        int half = lane >> 4, hl = lane & 15;
        int ln = warp*2 + half;
        float vv[4];
        float s1 = 0.f, s2 = 0.f;
        #pragma unroll
        for (int k = 0; k < 4; ++k) {
            vv[k] = sdw[ln*69 + hl*4 + k];
            s1 += vv[k]; s2 += vv[k]*vv[k];
        }
        #pragma unroll
        for (int off = 8; off; off >>= 1) {
            s1 += __shfl_xor_sync(0xffffffffu, s1, off);
            s2 += __shfl_xor_sync(0xffffffffu, s2, off);
        }
        float mu  = s1 * (1.f/64.f);
        float var = s2 * (1.f/64.f) - mu*mu;
        float rs  = rsqrtf(var + 1e-5f);
        float offy = 0.f, offx = 0.f;
        #pragma unroll
        for (int k = 0; k < 4; ++k) {
            int c = hl*4 + k;
            float t = (vv[k] - mu) * rs * __ldg(&lng[blk*64 + c]) + __ldg(&lnb[blk*64 + c]);
            float gl = 0.5f * t * (1.f + erff(t * 0.70710678118654752f));
            offy = fmaf(__ldg(&pww[blk*128 + c]),      gl, offy);
            offx = fmaf(__ldg(&pww[blk*128 + 64 + c]), gl, offx);
        }
        #pragma unroll
        for (int off = 8; off; off >>= 1) {
            offy += __shfl_xor_sync(0xffffffffu, offy, off);
            offx += __shfl_xor_sync(0xffffffffu, offx, off);
        }
        if (hl == 0) {
            int oy = tile;                          // dwconv output row
            float refy = (2.f*((float)oy + 0.5f)) * (1.f/15.f) - 1.f;
            float refx = (2.f*((float)ln + 0.5f)) * (1.f/15.f) - 1.f;
            float py = fminf(fmaxf(offy + refy, -1.f), 1.f);
            float px = fminf(fmaxf(offx + refx, -1.f), 1.f);
            float ay = 31.5f*(1.f - py), ax = 31.5f*(1.f - px);
            float by0 = floorf(ay), bx0 = floorf(ax);
            int n = tile*16 + ln;
            g_BP[bb*NS + n]  = make_float4(by0*127.f + bx0, ay - by0, ax - bx0, 0.f);
            g_POS[bb*NS + n] = make_float2(py, px);
        }
    }
}

// ============================================================================
// Kernel B3: deformable gather + k/v projections.
// grid = 384 (3 blk * 8 b * 16 n-chunks of 16), 256 threads = (nl 16, cg 16).
// Gather fully unrolled (16 independent LDGs up-front -> max MLP).
// ============================================================================
__global__ __launch_bounds__(256) void k_gkv(
    const float* __restrict__ x0, const float* __restrict__ x1,
    const float* __restrict__ pkw, const float* __restrict__ pkb,
    const float* __restrict__ pvw, const float* __restrict__ pvb)
{
    extern __shared__ float sm[];
    float* buf  = sm;               // [16][65] = 1040
    float* skwT = sm + 16*65;       // [c][o] 4096
    float* svwT = skwT + 4096;      // 4096

    int bx = blockIdx.x;
    int chunk = bx & 15, b = (bx >> 4) & 7, blk = bx >> 7;
    const float* kvsrc = (blk == 2 ? x1 : x0) + (size_t)b * 128 * HWQ;
    int tid = threadIdx.x;
    int nl = tid & 15, cg = tid >> 4;      // cg 0..15, 4 channels / 4 outputs
    int n = chunk*16 + nl;

    for (int i = tid; i < 4096; i += 256) {
        int o = i >> 6, c = i & 63;
        skwT[c*64 + o] = pkw[blk*4096 + i];
        svwT[c*64 + o] = pvw[blk*4096 + i];
    }

    float2 pos = g_POS[(blk*BD + b)*NS + n];
    float sy = (pos.x + 1.f)*31.5f, sx = (pos.y + 1.f)*31.5f;
    float fy = floorf(sy), fx = floorf(sx);
    int iy0 = (int)fy, ix0 = (int)fx;
    float wby = sy - fy, wbx = sx - fx;
    int iy1 = min(iy0 + 1, 63), ix1 = min(ix0 + 1, 63);
    float w00 = (1.f-wby)*(1.f-wbx), w01 = (1.f-wby)*wbx;
    float w10 = wby*(1.f-wbx),       w11 = wby*wbx;

    // all 16 taps issued before any dependent math (MLP)
    float tap[16];
    #pragma unroll
    for (int cc = 0; cc < 4; ++cc) {
        const float* ip = kvsrc + (size_t)(cg*4 + cc)*HWQ;
        tap[cc*4+0] = __ldg(&ip[iy0*64 + ix0]);
        tap[cc*4+1] = __ldg(&ip[iy0*64 + ix1]);
        tap[cc*4+2] = __ldg(&ip[iy1*64 + ix0]);
        tap[cc*4+3] = __ldg(&ip[iy1*64 + ix1]);
    }
    #pragma unroll
    for (int cc = 0; cc < 4; ++cc)
        buf[nl*65 + cg*4 + cc] = w00*tap[cc*4+0] + w01*tap[cc*4+1]
                               + w10*tap[cc*4+2] + w11*tap[cc*4+3];
    __syncthreads();

    float ak[4], av[4];
    #pragma unroll
    for (int oo = 0; oo < 4; ++oo) {
        ak[oo] = __ldg(&pkb[blk*64 + cg*4 + oo]);
        av[oo] = __ldg(&pvb[blk*64 + cg*4 + oo]);
    }
    #pragma unroll 8
    for (int c = 0; c < 64; ++c) {
        float xv = buf[nl*65 + c];
        float4 kw = *reinterpret_cast<const float4*>(&skwT[c*64 + cg*4]);
        float4 vw = *reinterpret_cast<const float4*>(&svwT[c*64 + cg*4]);
        ak[0] = fmaf(kw.x, xv, ak[0]); ak[1] = fmaf(kw.y, xv, ak[1]);
        ak[2] = fmaf(kw.z, xv, ak[2]); ak[3] = fmaf(kw.w, xv, ak[3]);
        av[0] = fmaf(vw.x, xv, av[0]); av[1] = fmaf(vw.y, xv, av[1]);
        av[2] = fmaf(vw.z, xv, av[2]); av[3] = fmaf(vw.w, xv, av[3]);
    }

    float* kout = g_K + (size_t)(blk*BD + b)*NCH*NS;
    float* vout = g_V + (size_t)(blk*BD + b)*NCH*NS;
    #pragma unroll
    for (int oo = 0; oo < 4; ++oo) {
        int o = cg*4 + oo;
        kout[o*NS + n] = ak[oo];
        vout[o*NS + n] = av[oo];
    }
}

// ============================================================================
// Kernel D: attention, packed f32x2 + depth-2 software pipeline on the
// indirect bias-table chain. One CTA per (bb,head,row-tile of 8).
// 256 threads, each = vertical query PAIR (rows y,y+1).
// ============================================================================
__global__ __launch_bounds__(256, 2) void k_attn()
{
    extern __shared__ float sm[];
    float*      Ks    = sm;                            // 4096 floats
    float*      Vs    = sm + 4096;                     // 4096 floats
    ulonglong2* ppw   = (ulonglong2*)(sm + 8192);      // 256 * 16B
    int*        pbase = (int*)(sm + 8192 + 1024);      // 256

    int bx = blockIdx.x;
    int tile = bx & 7, head = (bx >> 3) & 3, bb = bx >> 5;  // bb = blk*8+b
    int tid = threadIdx.x;

    const u64t* tab = (const u64t*)(g_TAB2 + (size_t)((bb >> 3)*4 + head) * TABP);

    const float* kg = g_K + (size_t)(bb*NCH + head*HCD) * NS;
    const float* vg = g_V + (size_t)(bb*NCH + head*HCD) * NS;
    #pragma unroll
    for (int c4 = 0; c4 < 4; ++c4) {
        float a0 = kg[(c4*4+0)*NS + tid], a1 = kg[(c4*4+1)*NS + tid];
        float a2 = kg[(c4*4+2)*NS + tid], a3 = kg[(c4*4+3)*NS + tid];
        reinterpret_cast<float4*>(Ks)[tid*4 + c4] = make_float4(a0,a1,a2,a3);
        a0 = vg[(c4*4+0)*NS + tid]; a1 = vg[(c4*4+1)*NS + tid];
        a2 = vg[(c4*4+2)*NS + tid]; a3 = vg[(c4*4+3)*NS + tid];
        reinterpret_cast<float4*>(Vs)[tid*4 + c4] = make_float4(a0,a1,a2,a3);
    }
    {
        float4 bp = g_BP[bb*NS + tid];
        float wy = bp.y, wx = bp.z;
        ulonglong2 w;
        w.x = pk2((1.f-wy)*(1.f-wx), (1.f-wy)*wx);   // (w00, w01)
        w.y = pk2(wy*(1.f-wx),       wy*wx);         // (w10, w11)
        ppw[tid] = w;
        pbase[tid] = (int)bp.x;
    }
    __syncthreads();

    int x = tid & 63, yp = tid >> 6;
    int y = tile*8 + yp*2;
    int m1 = y*64 + x;
    int rbase = y*127 + x;
    const float* qg = g_Q + (size_t)(bb*NCH + head*HCD) * HWQ;
    u64t q1p[8], q2p[8];
    #pragma unroll
    for (int j = 0; j < 8; ++j) {
        q1p[j] = pk2(qg[(2*j)*HWQ + m1],      qg[(2*j+1)*HWQ + m1]);
        q2p[j] = pk2(qg[(2*j)*HWQ + m1 + 64], qg[(2*j+1)*HWQ + m1 + 64]);
    }

    u64t acc1p[8], acc2p[8];
    u64t zero = pk2(0.f, 0.f);
    #pragma unroll
    for (int j = 0; j < 8; ++j) { acc1p[j] = zero; acc2p[j] = zero; }
    float ss1 = 0.f, ss2 = 0.f;

    const ulonglong2* Ksu = (const ulonglong2*)Ks;
    const ulonglong2* Vsu = (const ulonglong2*)Vs;

    // ---- pipeline prologue: preload slots for n=0,1 ----
    ulonglong2 wpp[2];
    u64t tt0[2], tt1[2], tt2[2];
    {
        int a0 = pbase[0] + rbase, a1 = pbase[1] + rbase;
        wpp[0] = ppw[0]; wpp[1] = ppw[1];
        tt0[0] = __ldg(&tab[a0]); tt1[0] = __ldg(&tab[a0+127]); tt2[0] = __ldg(&tab[a0+254]);
        tt0[1] = __ldg(&tab[a1]); tt1[1] = __ldg(&tab[a1+127]); tt2[1] = __ldg(&tab[a1+254]);
    }

    #pragma unroll 2
    for (int n = 0; n < 256; ++n) {
        int cur = n & 1;
        ulonglong2 wp = wpp[cur];
        u64t t0 = tt0[cur], t1 = tt1[cur], t2 = tt2[cur];
        int np = n + 2;
        if (np < 256) {
            int a = pbase[np] + rbase;
            wpp[cur] = ppw[np];
            tt0[cur] = __ldg(&tab[a]);
            tt1[cur] = __ldg(&tab[a + 127]);
            tt2[cur] = __ldg(&tab[a + 254]);
        }

        u64t b1p = fma2(wp.y, t1, mul2(wp.x, t0));
        u64t b2p = fma2(wp.y, t2, mul2(wp.x, t1));
        float2 b1u = upk2(b1p), b2u = upk2(b2p);
        float b1 = b1u.x + b1u.y, b2 = b2u.x + b2u.y;

        ulonglong2 kA = Ksu[n*4+0], kB = Ksu[n*4+1], kC = Ksu[n*4+2], kD = Ksu[n*4+3];
        u64t d1p = mul2(q1p[0], kA.x);
        d1p = fma2(q1p[1], kA.y, d1p); d1p = fma2(q1p[2], kB.x, d1p);
        d1p = fma2(q1p[3], kB.y, d1p); d1p = fma2(q1p[4], kC.x, d1p);
        d1p = fma2(q1p[5], kC.y, d1p); d1p = fma2(q1p[6], kD.x, d1p);
        d1p = fma2(q1p[7], kD.y, d1p);
        u64t d2p = mul2(q2p[0], kA.x);
        d2p = fma2(q2p[1], kA.y, d2p); d2p = fma2(q2p[2], kB.x, d2p);
        d2p = fma2(q2p[3], kB.y, d2p); d2p = fma2(q2p[4], kC.x, d2p);
        d2p = fma2(q2p[5], kC.y, d2p); d2p = fma2(q2p[6], kD.x, d2p);
        d2p = fma2(q2p[7], kD.y, d2p);
        float2 d1u = upk2(d1p), d2u = upk2(d2p);
        float d1 = d1u.x + d1u.y, d2 = d2u.x + d2u.y;

        float p1 = __expf(fmaf(d1, 0.25f, b1)); ss1 += p1;
        float p2 = __expf(fmaf(d2, 0.25f, b2)); ss2 += p2;
        u64t p1p = pk2(p1, p1), p2p = pk2(p2, p2);

        ulonglong2 vA = Vsu[n*4+0], vB = Vsu[n*4+1], vC = Vsu[n*4+2], vD = Vsu[n*4+3];
        acc1p[0] = fma2(p1p, vA.x, acc1p[0]); acc2p[0] = fma2(p2p, vA.x, acc2p[0]);
        acc1p[1] = fma2(p1p, vA.y, acc1p[1]); acc2p[1] = fma2(p2p, vA.y, acc2p[1]);
        acc1p[2] = fma2(p1p, vB.x, acc1p[2]); acc2p[2] = fma2(p2p, vB.x, acc2p[2]);
        acc1p[3] = fma2(p1p, vB.y, acc1p[3]); acc2p[3] = fma2(p2p, vB.y, acc2p[3]);
        acc1p[4] = fma2(p1p, vC.x, acc1p[4]); acc2p[4] = fma2(p2p, vC.x, acc2p[4]);
        acc1p[5] = fma2(p1p, vC.y, acc1p[5]); acc2p[5] = fma2(p2p, vC.y, acc2p[5]);
        acc1p[6] = fma2(p1p, vD.x, acc1p[6]); acc2p[6] = fma2(p2p, vD.x, acc2p[6]);
        acc1p[7] = fma2(p1p, vD.y, acc1p[7]); acc2p[7] = fma2(p2p, vD.y, acc2p[7]);
    }

    float i1 = 1.f / ss1, i2 = 1.f / ss2;
    float* og = g_O + (size_t)(bb*NCH + head*HCD) * HWQ;
    #pragma unroll
    for (int j = 0; j < 8; ++j) {
        float2 a1 = upk2(acc1p[j]), a2 = upk2(acc2p[j]);
        og[(2*j  )*HWQ + m1]      = a1.x * i1;
        og[(2*j+1)*HWQ + m1]      = a1.y * i1;
        og[(2*j  )*HWQ + m1 + 64] = a2.x * i2;
        og[(2*j+1)*HWQ + m1 + 64] = a2.y * i2;
    }
}

// ============================================================================
// Kernel E: output projection + residual for channels 64..127, levels 1 & 2
// only (passthrough handled by memcpy nodes). grid = 256, 256 threads.
// ============================================================================
__global__ __launch_bounds__(256) void k_out(
    const float* __restrict__ x1, const float* __restrict__ x2,
    const float* __restrict__ poww, const float* __restrict__ pob,
    float* __restrict__ out)
{
    __shared__ float wsT[2][64*64];
    __shared__ float bsum[64];
    int bx = blockIdx.x;
    int tile = bx & 15, b = (bx >> 4) & 7, lvl = 1 + (bx >> 7);
    const float* xl = (lvl == 1 ? x1 : x2) + (size_t)b * 128 * HWQ;
    float* outp = out + (size_t)(lvl*BD + b) * 128 * HWQ;
    int hw = tile*256 + threadIdx.x;

    int blk0 = (lvl == 1) ? 0 : 1;
    int nb   = (lvl == 1) ? 1 : 2;

    for (int i = threadIdx.x; i < 4096; i += 256) {
        int c = i >> 6, o = i & 63;
        wsT[0][c*64 + o] = poww[blk0*4096 + o*64 + c];
        if (nb == 2) wsT[1][c*64 + o] = poww[(blk0+1)*4096 + o*64 + c];
    }
    if (threadIdx.x < 64) {
        float s = pob[blk0*64 + threadIdx.x];
        if (nb == 2) s += pob[(blk0+1)*64 + threadIdx.x];
        bsum[threadIdx.x] = s;
    }
    __syncthreads();

    const float* o0 = g_O + (size_t)(blk0*BD + b) * NCH * HWQ;
    const float* o1 = g_O + (size_t)((blk0+1)*BD + b) * NCH * HWQ;

    float acc[64];
    #pragma unroll
    for (int o = 0; o < 64; ++o)
        acc[o] = __ldg(&xl[(64 + o)*HWQ + hw]) + bsum[o];

    #pragma unroll 2
    for (int c = 0; c < 64; ++c) {
        float a0 = o0[c*HWQ + hw];
        const float4* wr = reinterpret_cast<const float4*>(&wsT[0][c*64]);
        #pragma unroll
        for (int o4 = 0; o4 < 16; ++o4) {
            float4 w = wr[o4];
            acc[o4*4+0] = fmaf(w.x, a0, acc[o4*4+0]);
            acc[o4*4+1] = fmaf(w.y, a0, acc[o4*4+1]);
            acc[o4*4+2] = fmaf(w.z, a0, acc[o4*4+2]);
            acc[o4*4+3] = fmaf(w.w, a0, acc[o4*4+3]);
        }
    }
    if (nb == 2) {
        #pragma unroll 2
        for (int c = 0; c < 64; ++c) {
            float a1 = o1[c*HWQ + hw];
            const float4* wr = reinterpret_cast<const float4*>(&wsT[1][c*64]);
            #pragma unroll
            for (int o4 = 0; o4 < 16; ++o4) {
                float4 w = wr[o4];
                acc[o4*4+0] = fmaf(w.x, a1, acc[o4*4+0]);
                acc[o4*4+1] = fmaf(w.y, a1, acc[o4*4+1]);
                acc[o4*4+2] = fmaf(w.z, a1, acc[o4*4+2]);
                acc[o4*4+3] = fmaf(w.w, a1, acc[o4*4+3]);
            }
        }
    }
    #pragma unroll
    for (int o = 0; o < 64; ++o)
        outp[(64 + o)*HWQ + hw] = acc[o];
}

// ============================================================================
extern "C" void kernel_launch(void* const* d_in, const int* in_sizes, int n_in,
                              void* d_out, int out_size)
{
    const float* x0  = (const float*)d_in[0];
    const float* x1  = (const float*)d_in[1];
    const float* x2  = (const float*)d_in[2];
    const float* pqw = (const float*)d_in[3];
    const float* pqb = (const float*)d_in[4];
    const float* dww = (const float*)d_in[5];
    const float* dwb = (const float*)d_in[6];
    const float* lng = (const float*)d_in[7];
    const float* lnb = (const float*)d_in[8];
    const float* pww = (const float*)d_in[9];
    const float* pkw = (const float*)d_in[10];
    const float* pkb = (const float*)d_in[11];
    const float* pvw = (const float*)d_in[12];
    const float* pvb = (const float*)d_in[13];
    const float* pow_ = (const float*)d_in[14];
    const float* pob = (const float*)d_in[15];
    const float* rpe = (const float*)d_in[16];
    float* out = (float*)d_out;

    const int gkv_smem = (16*65 + 4096 + 4096) * 4;            // 36928 B
    const int d_smem   = 8192*4 + 256*16 + 256*4;              // 37888 B
    cudaFuncSetAttribute(k_gkv,  cudaFuncAttributeMaxDynamicSharedMemorySize, gkv_smem);
    cudaFuncSetAttribute(k_attn, cudaFuncAttributeMaxDynamicSharedMemorySize, d_smem);

    const size_t LVL = (size_t)BD * 128 * HWQ;
    const size_t BAT = (size_t)128 * HWQ;

    cudaMemcpyAsync(out, x0, LVL * 4, cudaMemcpyDeviceToDevice);
    for (int b = 0; b < BD; ++b)
        cudaMemcpyAsync(out + LVL + b*BAT, x1 + b*BAT, (BAT/2) * 4,
                        cudaMemcpyDeviceToDevice);
    for (int b = 0; b < BD; ++b)
        cudaMemcpyAsync(out + 2*LVL + b*BAT, x2 + b*BAT, (BAT/2) * 4,
                        cudaMemcpyDeviceToDevice);

    k_tab2<<<96, 256>>>(rpe);
    k_qproj_dw<<<384, 256>>>(x1, x2, pqw, pqb, dww, dwb, lng, lnb, pww);
    k_gkv<<<384, 256, gkv_smem>>>(x0, x1, pkw, pkb, pvw, pvb);
    k_attn<<<768, 256, d_smem>>>();
    k_out<<<256, 256>>>(x1, x2, pow_, pob, out);
}